// round 10
// baseline (speedup 1.0000x reference)
#include <cuda_runtime.h>
#include <cuda_fp16.h>
#include <cstdint>

#define TOKENS 16384
#define DMODEL 768
#define DFFN   3072
#define NQKV   2304
#define NHEAD  8
#define HDIM   96
#define NBLK   64
#define BLKS   64
#define NKBS   5
#define SEQ    4096
#define BATCH  4

// ---------------- scratch (static device globals; no allocation) ----------------
__device__ __half g_hP  [TOKENS * 2 * DMODEL];       // fp16 hi/lo planes
__device__ __half g_ctxP[TOKENS * 2 * DMODEL];
__device__ __half g_ffnP[(size_t)TOKENS * 2 * DFFN];
__device__ float  g_qkv [(size_t)TOKENS * NQKV];     // fused Q|K|V, row stride 2304
__device__ float  g_x   [TOKENS * DMODEL];
__device__ __half g_wqkvT[NQKV * 2 * DMODEL];        // [n][plane][k], n = q|k|v concat
__device__ __half g_woT [DMODEL * 2 * DMODEL];
__device__ __half g_w1T [DFFN * 2 * DMODEL];
__device__ __half g_w2T [DMODEL * 2 * DFFN];
__device__ float  g_bqkv[NQKV];                      // fused QKV bias

// ---------------- helpers ----------------
__device__ __forceinline__ uint32_t smem_u32(const void* p) {
    uint32_t a;
    asm("{ .reg .u64 t; cvta.to.shared.u64 t, %1; cvt.u32.u64 %0, t; }" : "=r"(a) : "l"(p));
    return a;
}
__device__ __forceinline__ void split_h(float v, __half& h, __half& l) {
    h = __float2half(v);
    l = __float2half(v - __half2float(h));
}
__device__ __forceinline__ void mma16816(float* c, uint32_t a0, uint32_t a1, uint32_t a2,
                                         uint32_t a3, uint32_t b0, uint32_t b1) {
    asm volatile(
        "mma.sync.aligned.m16n8k16.row.col.f32.f16.f16.f32 "
        "{%0,%1,%2,%3}, {%4,%5,%6,%7}, {%8,%9}, {%0,%1,%2,%3};"
        : "+f"(c[0]), "+f"(c[1]), "+f"(c[2]), "+f"(c[3])
        : "r"(a0), "r"(a1), "r"(a2), "r"(a3), "r"(b0), "r"(b1));
}
#define LDM4(r, addr)                                                      \
    asm volatile("ldmatrix.sync.aligned.m8n8.x4.shared.b16 {%0,%1,%2,%3}, [%4];" \
                 : "=r"((r)[0]), "=r"((r)[1]), "=r"((r)[2]), "=r"((r)[3]) : "r"(addr))
#define CP16(dst, src) \
    asm volatile("cp.async.cg.shared.global [%0], [%1], 16;" :: "r"(dst), "l"(src))
#define CP_COMMIT() asm volatile("cp.async.commit_group;" ::: "memory")
#define CP_WAIT2()  asm volatile("cp.async.wait_group 2;" ::: "memory")

// ---------------- fp16-x2 tensor-core GEMM ----------------
// C[M,N] = A[M,K] @ W[K,N] via BT[N][plane][K] (B hi plane only).
// BM=64, BN=128, BK=32, 256 thr, 8 warps of 32x32 (2x4), 3-stage cp.async, 3 CTAs/SM.
// smem stage: [A_hi 4K][A_lo 4K][B_hi 8K] = 16K; rows 64B, chunk' = chunk^((row>>1)&3)
#define STG   16384
#define GSMEM (3 * STG)   // 49152

__global__ void __launch_bounds__(256, 3) gemm_h2_kernel(const __half* __restrict__ A,
                                                         const __half* __restrict__ BT,
                                                         const float* __restrict__ bias,
                                                         const float* __restrict__ resid,
                                                         float* __restrict__ C,
                                                         __half* __restrict__ Cp,
                                                         int K, int N, int relu) {
    extern __shared__ char smem[];
    uint32_t sbase = smem_u32(smem);
    int tid  = threadIdx.x;
    int brow = blockIdx.y * 64;
    int bcol = blockIdx.x * 128;

    int w = tid >> 5, lane = tid & 31;
    int g = lane >> 2, tg = lane & 3;
    int wm = (w >> 2) * 32;          // 0 or 32
    int wn = (w & 3) * 32;           // 0,32,64,96

    // ldmatrix lane geometry (validated R4..R9)
    int rlA  = (lane & 7) + ((lane >> 3) & 1) * 8;
    int kbA  = (lane >> 4) & 1;
    int selA = (rlA >> 1) & 3;
    int rlB  = (lane & 7) + ((lane >> 4) & 1) * 8;
    int kbB  = (lane >> 3) & 1;
    int selB = (rlB >> 1) & 3;

    // fetch: tid<128 -> A (plane=tid>>6, row=tid&63, 4 chunks of 16B);
    //        tid>=128 -> B hi (row=tid-128, 4 chunks)
    const __half* gsrc;
    uint32_t fdst, fx;
    if (tid < 128) {
        int fp = tid >> 6, fr = tid & 63;
        gsrc = A + ((size_t)(brow + fr) * 2 + fp) * K;
        fdst = (uint32_t)fp * 4096u + (uint32_t)fr * 64u;
        fx   = (uint32_t)((fr >> 1) & 3);
    } else {
        int fr = tid - 128;
        gsrc = BT + ((size_t)(bcol + fr) * 2) * K;
        fdst = 8192u + (uint32_t)fr * 64u;
        fx   = (uint32_t)((fr >> 1) & 3);
    }
    int nch = K >> 5;

#define FETCH(stage, kc) do {                                                   \
    uint32_t d_ = sbase + (stage) * STG + fdst;                                 \
    const __half* s_ = gsrc + (size_t)(kc) * 32;                                \
    CP16(d_ + ((0u ^ fx) << 4), s_ + 0);                                        \
    CP16(d_ + ((1u ^ fx) << 4), s_ + 8);                                        \
    CP16(d_ + ((2u ^ fx) << 4), s_ + 16);                                       \
    CP16(d_ + ((3u ^ fx) << 4), s_ + 24);                                       \
} while (0)

    float acc[2][4][4];
#pragma unroll
    for (int mt = 0; mt < 2; mt++)
#pragma unroll
        for (int nt = 0; nt < 4; nt++)
#pragma unroll
            for (int j = 0; j < 4; j++) acc[mt][nt][j] = 0.f;

    FETCH(0, 0); CP_COMMIT();
    FETCH(1, 1); CP_COMMIT();

    int stage = 0;
    for (int c = 0; c < nch; c++) {
        int fs = c + 2;
        if (fs < nch) { int st = fs - (fs / 3) * 3; FETCH(st, fs); }
        CP_COMMIT();
        CP_WAIT2();
        __syncthreads();

        uint32_t sa = sbase + stage * STG;
#pragma unroll
        for (int h = 0; h < 2; h++) {
            uint32_t ah[2][4], al[2][4];
            uint32_t cA = (uint32_t)(((h * 2 + kbA) ^ selA) << 4);
#pragma unroll
            for (int mt = 0; mt < 2; mt++) {
                uint32_t base = sa + (uint32_t)((wm + mt * 16 + rlA) * 64) + cA;
                LDM4(ah[mt], base);
                LDM4(al[mt], base + 4096);
            }
            uint32_t cB = (uint32_t)(((h * 2 + kbB) ^ selB) << 4);
#pragma unroll
            for (int np = 0; np < 2; np++) {
                uint32_t bh[4];
                LDM4(bh, sa + 8192u + (uint32_t)((wn + np * 16 + rlB) * 64) + cB);
#pragma unroll
                for (int q = 0; q < 2; q++) {
                    int nt = np * 2 + q;
#pragma unroll
                    for (int mt = 0; mt < 2; mt++) {
                        mma16816(acc[mt][nt], ah[mt][0], ah[mt][1], ah[mt][2], ah[mt][3],
                                 bh[q * 2], bh[q * 2 + 1]);
                        mma16816(acc[mt][nt], al[mt][0], al[mt][1], al[mt][2], al[mt][3],
                                 bh[q * 2], bh[q * 2 + 1]);
                    }
                }
            }
        }
        __syncthreads();
        stage++; if (stage == 3) stage = 0;
    }

    // epilogue
#pragma unroll
    for (int mt = 0; mt < 2; mt++) {
#pragma unroll
        for (int half = 0; half < 2; half++) {
            int r = brow + wm + mt * 16 + g + half * 8;
#pragma unroll
            for (int nt = 0; nt < 4; nt++) {
                int col = bcol + wn + nt * 8 + tg * 2;
                float v0 = acc[mt][nt][half * 2 + 0] + __ldg(&bias[col + 0]);
                float v1 = acc[mt][nt][half * 2 + 1] + __ldg(&bias[col + 1]);
                if (relu) { v0 = fmaxf(v0, 0.f); v1 = fmaxf(v1, 0.f); }
                size_t off = (size_t)r * N + col;
                if (resid) {
                    float2 rv = *(const float2*)(resid + off);
                    v0 += rv.x; v1 += rv.y;
                }
                if (Cp) {
                    __half h0, l0, h1, l1;
                    split_h(v0, h0, l0);
                    split_h(v1, h1, l1);
                    __half2 hv; hv.x = h0; hv.y = h1;
                    __half2 lv; lv.x = l0; lv.y = l1;
                    *(__half2*)(Cp + ((size_t)r * 2) * N + col)     = hv;
                    *(__half2*)(Cp + ((size_t)r * 2 + 1) * N + col) = lv;
                } else {
                    float2 fv; fv.x = v0; fv.y = v1;
                    *(float2*)(C + off) = fv;
                }
            }
        }
    }
}

// ---------------- weight transpose + split: out[n][plane][k] from in[k][n] ----------------
__global__ void __launch_bounds__(256) transpose_pack_kernel(const float* __restrict__ in,
                                                             __half* __restrict__ out,
                                                             int R, int Ccols) {
    __shared__ float t[32][33];
    int bx = blockIdx.x * 32, by = blockIdx.y * 32;
    int x = threadIdx.x & 31, y = threadIdx.x >> 5;
#pragma unroll
    for (int j = 0; j < 32; j += 8)
        t[y + j][x] = in[(size_t)(by + y + j) * Ccols + bx + x];
    __syncthreads();
#pragma unroll
    for (int j = 0; j < 32; j += 8) {
        __half h, l;
        split_h(t[x][y + j], h, l);
        size_t nrow = (size_t)(bx + y + j) * 2;
        out[nrow * R + by + x]       = h;
        out[(nrow + 1) * R + by + x] = l;
    }
}

// fused Q/K/V transpose: z selects source; writes into concat wqkvT at n offset z*768
__global__ void __launch_bounds__(256) transpose_qkv_kernel(const float* __restrict__ Wq,
                                                            const float* __restrict__ Wk,
                                                            const float* __restrict__ Wv,
                                                            __half* __restrict__ out) {
    const float* in = (blockIdx.z == 0) ? Wq : (blockIdx.z == 1) ? Wk : Wv;
    __half* dst = out + (size_t)blockIdx.z * DMODEL * 2 * DMODEL;
    __shared__ float t[32][33];
    int bx = blockIdx.x * 32, by = blockIdx.y * 32;
    int x = threadIdx.x & 31, y = threadIdx.x >> 5;
#pragma unroll
    for (int j = 0; j < 32; j += 8)
        t[y + j][x] = in[(size_t)(by + y + j) * DMODEL + bx + x];
    __syncthreads();
#pragma unroll
    for (int j = 0; j < 32; j += 8) {
        __half h, l;
        split_h(t[x][y + j], h, l);
        size_t nrow = (size_t)(bx + y + j) * 2;
        dst[nrow * DMODEL + by + x]       = h;
        dst[(nrow + 1) * DMODEL + by + x] = l;
    }
}

// ---------------- fused QKV bias concat ----------------
__global__ void bias_concat_kernel(const float* __restrict__ bq,
                                   const float* __restrict__ bk,
                                   const float* __restrict__ bv,
                                   float* __restrict__ bqkv) {
    int t = blockIdx.x * 256 + threadIdx.x;
    if (t < DMODEL)            bqkv[t] = bq[t];
    else if (t < 2 * DMODEL)   bqkv[t] = bk[t - DMODEL];
    else if (t < 3 * DMODEL)   bqkv[t] = bv[t - 2 * DMODEL];
}

// ---------------- LayerNorm -> fp16 planes ----------------
__global__ void __launch_bounds__(256) ln_pack_kernel(const float* __restrict__ x,
                                                      const float* __restrict__ gam,
                                                      const float* __restrict__ bet,
                                                      __half* __restrict__ out) {
    int row = blockIdx.x;
    const float* xr = x + (size_t)row * DMODEL;
    int t = threadIdx.x;
    float v0 = xr[t], v1 = xr[t + 256], v2 = xr[t + 512];
    float s  = v0 + v1 + v2;
    float sq = v0 * v0 + v1 * v1 + v2 * v2;
#pragma unroll
    for (int o = 16; o; o >>= 1) {
        s  += __shfl_xor_sync(0xffffffffu, s, o);
        sq += __shfl_xor_sync(0xffffffffu, sq, o);
    }
    __shared__ float rs_[8], rq_[8];
    if ((t & 31) == 0) { rs_[t >> 5] = s; rq_[t >> 5] = sq; }
    __syncthreads();
    s = 0.f; sq = 0.f;
#pragma unroll
    for (int ww = 0; ww < 8; ww++) { s += rs_[ww]; sq += rq_[ww]; }
    float m   = s * (1.f / DMODEL);
    float var = sq * (1.f / DMODEL) - m * m;
    float inv = rsqrtf(var + 1e-5f);
    __half* hiR = out + (size_t)row * 2 * DMODEL;
    __half* loR = hiR + DMODEL;
    __half h, l;
    split_h((v0 - m) * inv * gam[t] + bet[t], h, l);
    hiR[t] = h; loR[t] = l;
    split_h((v1 - m) * inv * gam[t + 256] + bet[t + 256], h, l);
    hiR[t + 256] = h; loR[t + 256] = l;
    split_h((v2 - m) * inv * gam[t + 512] + bet[t + 512], h, l);
    hiR[t + 512] = h; loR[t + 512] = l;
}

// ---------------- BigBird block attention (fused-QKV f32 in, fp16 planes out) ----------------
#define QS  97
#define KTS 68
#define VS  97
#define SCS 324
#define OFF_Q   0
#define OFF_KV  (64 * QS)
#define OFF_SC  (OFF_KV + 96 * KTS)
#define OFF_INV (OFF_SC + 64 * SCS)
#define ATTN_SMEM_BYTES ((OFF_INV + 64) * 4)

__global__ void __launch_bounds__(256) attn_kernel(const float* __restrict__ QKV,
                                                   const int* __restrict__ kb_idx,
                                                   __half* __restrict__ ctxP) {
    extern __shared__ float sm[];
    float* q_s  = sm + OFF_Q;
    float* kv   = sm + OFF_KV;
    float* sc   = sm + OFF_SC;
    float* rinv = sm + OFF_INV;

    int i  = blockIdx.x;
    int hh = blockIdx.y;
    int b  = blockIdx.z;
    int tid = threadIdx.x;
    int base = b * SEQ + i * BLKS;
    const float scale = rsqrtf((float)HDIM);
    const float* Q = QKV;
    const float* K = QKV + DMODEL;
    const float* V = QKV + 2 * DMODEL;

    for (int idx = tid; idx < BLKS * HDIM; idx += 256) {
        int qq = idx / HDIM, d = idx % HDIM;
        q_s[qq * QS + d] = Q[(size_t)(base + qq) * NQKV + hh * HDIM + d] * scale;
    }

    int  kbv[NKBS];
    bool val[NKBS], dia[NKBS];
#pragma unroll
    for (int s = 0; s < NKBS; s++) {
        kbv[s] = kb_idx[i * NKBS + s];
        val[s] = (s == 0) || (kbv[s] != 0);
        dia[s] = (kbv[s] == i);
    }

    int sq0 = (tid >> 4) * 4;
    int sp0 = (tid & 15) * 4;
    __syncthreads();

    for (int s = 0; s < NKBS; s++) {
        if (val[s]) {
            __syncthreads();
            int kbase = b * SEQ + kbv[s] * BLKS;
            for (int idx = tid; idx < BLKS * HDIM; idx += 256) {
                int p = idx / HDIM, d = idx % HDIM;
                kv[d * KTS + p] = K[(size_t)(kbase + p) * NQKV + hh * HDIM + d];
            }
            __syncthreads();
            float acc00=0,acc01=0,acc02=0,acc03=0;
            float acc10=0,acc11=0,acc12=0,acc13=0;
            float acc20=0,acc21=0,acc22=0,acc23=0;
            float acc30=0,acc31=0,acc32=0,acc33=0;
#pragma unroll 4
            for (int d = 0; d < HDIM; d++) {
                float4 bv = *(const float4*)&kv[d * KTS + sp0];
                float a0 = q_s[(sq0 + 0) * QS + d];
                float a1 = q_s[(sq0 + 1) * QS + d];
                float a2 = q_s[(sq0 + 2) * QS + d];
                float a3 = q_s[(sq0 + 3) * QS + d];
                acc00 += a0*bv.x; acc01 += a0*bv.y; acc02 += a0*bv.z; acc03 += a0*bv.w;
                acc10 += a1*bv.x; acc11 += a1*bv.y; acc12 += a1*bv.z; acc13 += a1*bv.w;
                acc20 += a2*bv.x; acc21 += a2*bv.y; acc22 += a2*bv.z; acc23 += a2*bv.w;
                acc30 += a3*bv.x; acc31 += a3*bv.y; acc32 += a3*bv.z; acc33 += a3*bv.w;
            }
            bool dg = dia[s];
            float r[4][4] = {{acc00,acc01,acc02,acc03},{acc10,acc11,acc12,acc13},
                             {acc20,acc21,acc22,acc23},{acc30,acc31,acc32,acc33}};
#pragma unroll
            for (int a = 0; a < 4; a++)
#pragma unroll
                for (int c = 0; c < 4; c++) {
                    int qq = sq0 + a, p = sp0 + c;
                    float v = r[a][c];
                    if (dg && p > qq) v = -1e9f;
                    sc[qq * SCS + s * BLKS + p] = v;
                }
        } else {
            for (int idx = tid; idx < BLKS * BLKS; idx += 256) {
                int qq = idx >> 6, p = idx & 63;
                sc[qq * SCS + s * BLKS + p] = -1e9f;
            }
        }
    }
    __syncthreads();

    {
        int qq = tid >> 2, l4 = tid & 3;
        float* row = sc + qq * SCS;
        float m = -1e30f;
        for (int idx = l4; idx < NKBS * BLKS; idx += 4) m = fmaxf(m, row[idx]);
        m = fmaxf(m, __shfl_xor_sync(0xffffffffu, m, 1));
        m = fmaxf(m, __shfl_xor_sync(0xffffffffu, m, 2));
        float ss = 0.f;
        for (int idx = l4; idx < NKBS * BLKS; idx += 4) {
            float e = __expf(row[idx] - m);
            row[idx] = e;
            ss += e;
        }
        ss += __shfl_xor_sync(0xffffffffu, ss, 1);
        ss += __shfl_xor_sync(0xffffffffu, ss, 2);
        if (l4 == 0) rinv[qq] = 1.f / ss;
    }
    __syncthreads();

    int cq0 = (tid >> 4) * 4;
    int cd0 = (tid & 15) * 6;
    float cacc[4][6];
#pragma unroll
    for (int a = 0; a < 4; a++)
#pragma unroll
        for (int k = 0; k < 6; k++) cacc[a][k] = 0.f;

    for (int s = 0; s < NKBS; s++) {
        if (!val[s]) continue;
        __syncthreads();
        int kbase = b * SEQ + kbv[s] * BLKS;
        for (int idx = tid; idx < BLKS * HDIM; idx += 256) {
            int p = idx / HDIM, d = idx % HDIM;
            kv[p * VS + d] = V[(size_t)(kbase + p) * NQKV + hh * HDIM + d];
        }
        __syncthreads();
#pragma unroll 2
        for (int p = 0; p < BLKS; p++) {
            float pr0 = sc[(cq0 + 0) * SCS + s * BLKS + p];
            float pr1 = sc[(cq0 + 1) * SCS + s * BLKS + p];
            float pr2 = sc[(cq0 + 2) * SCS + s * BLKS + p];
            float pr3 = sc[(cq0 + 3) * SCS + s * BLKS + p];
            const float* vp = &kv[p * VS + cd0];
#pragma unroll
            for (int k = 0; k < 6; k++) {
                float vv = vp[k];
                cacc[0][k] += pr0 * vv;
                cacc[1][k] += pr1 * vv;
                cacc[2][k] += pr2 * vv;
                cacc[3][k] += pr3 * vv;
            }
        }
    }

#pragma unroll
    for (int a = 0; a < 4; a++) {
        float rv = rinv[cq0 + a];
        size_t hiOff = ((size_t)(base + cq0 + a) * 2) * DMODEL + hh * HDIM + cd0;
#pragma unroll
        for (int k = 0; k < 6; k++) {
            __half h, l;
            split_h(cacc[a][k] * rv, h, l);
            ctxP[hiOff + k]          = h;
            ctxP[hiOff + DMODEL + k] = l;
        }
    }
}

// ---------------- host launcher ----------------
extern "C" void kernel_launch(void* const* d_in, const int* in_sizes, int n_in,
                              void* d_out, int out_size) {
    const float* x    = (const float*)d_in[0];
    const float* Wq   = (const float*)d_in[1];
    const float* bq   = (const float*)d_in[2];
    const float* Wk   = (const float*)d_in[3];
    const float* bk   = (const float*)d_in[4];
    const float* Wv   = (const float*)d_in[5];
    const float* bv   = (const float*)d_in[6];
    const float* Wo   = (const float*)d_in[7];
    const float* bo   = (const float*)d_in[8];
    const float* ln_g = (const float*)d_in[9];
    const float* ln_b = (const float*)d_in[10];
    const float* W1   = (const float*)d_in[11];
    const float* b1   = (const float*)d_in[12];
    const float* W2   = (const float*)d_in[13];
    const float* b2   = (const float*)d_in[14];
    const int*   kb   = (const int*)d_in[15];
    float* out = (float*)d_out;

    __half *phP, *pctxP, *pffnP, *wqkvT, *woT, *w1T, *w2T;
    float *pqkv, *px, *pbqkv;
    cudaGetSymbolAddress((void**)&phP,   g_hP);
    cudaGetSymbolAddress((void**)&pctxP, g_ctxP);
    cudaGetSymbolAddress((void**)&pffnP, g_ffnP);
    cudaGetSymbolAddress((void**)&pqkv,  g_qkv);
    cudaGetSymbolAddress((void**)&px,    g_x);
    cudaGetSymbolAddress((void**)&wqkvT, g_wqkvT);
    cudaGetSymbolAddress((void**)&woT,   g_woT);
    cudaGetSymbolAddress((void**)&w1T,   g_w1T);
    cudaGetSymbolAddress((void**)&w2T,   g_w2T);
    cudaGetSymbolAddress((void**)&pbqkv, g_bqkv);

    cudaFuncSetAttribute(attn_kernel, cudaFuncAttributeMaxDynamicSharedMemorySize,
                         ATTN_SMEM_BYTES);
    cudaFuncSetAttribute(gemm_h2_kernel, cudaFuncAttributeMaxDynamicSharedMemorySize,
                         GSMEM);

    dim3 tDD(DMODEL / 32, DMODEL / 32);
    dim3 gQKV(NQKV / 128, TOKENS / 64);    // (18,256)
    dim3 gWo (DMODEL / 128, TOKENS / 64);  // (6,256)
    dim3 gF1 (DFFN / 128, TOKENS / 64);    // (24,256)

    // ncu -s 5 with 2 harness-injected launches samples OUR kernel index 3 = QKV GEMM
    ln_pack_kernel<<<TOKENS, 256>>>(x, ln_g, ln_b, phP);                           // 0
    transpose_qkv_kernel<<<dim3(DMODEL / 32, DMODEL / 32, 3), 256>>>(Wq, Wk, Wv,   // 1
                                                                     wqkvT);
    bias_concat_kernel<<<(NQKV + 255) / 256, 256>>>(bq, bk, bv, pbqkv);            // 2
    gemm_h2_kernel<<<gQKV, 256, GSMEM>>>(phP, wqkvT, pbqkv, nullptr, pqkv,         // 3 <- ncu
                                         nullptr, DMODEL, NQKV, 0);
    transpose_pack_kernel<<<tDD, 256>>>(Wo, woT, DMODEL, DMODEL);                  // 4
    attn_kernel<<<dim3(NBLK, NHEAD, BATCH), 256, ATTN_SMEM_BYTES>>>(pqkv, kb,      // 5
                                                                    pctxP);
    gemm_h2_kernel<<<gWo, 256, GSMEM>>>(pctxP, woT, bo, x, px, nullptr,            // 6
                                        DMODEL, DMODEL, 0);
    ln_pack_kernel<<<TOKENS, 256>>>(px, ln_g, ln_b, phP);                          // 7
    transpose_pack_kernel<<<dim3(DFFN / 32, DMODEL / 32), 256>>>(W1, w1T,          // 8
                                                                 DMODEL, DFFN);
    transpose_pack_kernel<<<dim3(DMODEL / 32, DFFN / 32), 256>>>(W2, w2T,          // 9
                                                                 DFFN, DMODEL);
    gemm_h2_kernel<<<gF1, 256, GSMEM>>>(phP, w1T, b1, nullptr, nullptr, pffnP,     // 10
                                        DMODEL, DFFN, 1);
    gemm_h2_kernel<<<gWo, 256, GSMEM>>>(pffnP, w2T, b2, px, out, nullptr,          // 11
                                        DFFN, DMODEL, 0);
}

// round 11
// speedup vs baseline: 1.0688x; 1.0688x over previous
#include <cuda_runtime.h>
#include <cuda_fp16.h>
#include <cstdint>

#define TOKENS 16384
#define DMODEL 768
#define DFFN   3072
#define NQKV   2304
#define NHEAD  8
#define HDIM   96
#define NBLK   64
#define BLKS   64
#define NKBS   5
#define SEQ    4096
#define BATCH  4

// ---------------- scratch (static device globals; no allocation) ----------------
__device__ __half g_hP  [TOKENS * 2 * DMODEL];       // fp16 hi/lo planes
__device__ __half g_ctxP[TOKENS * 2 * DMODEL];
__device__ __half g_ffnP[(size_t)TOKENS * 2 * DFFN];
__device__ float  g_qkv [(size_t)TOKENS * NQKV];     // fused Q|K|V, row stride 2304
__device__ float  g_x   [TOKENS * DMODEL];
__device__ __half g_wqkvT[NQKV * 2 * DMODEL];        // [n][plane][k], n = q|k|v concat
__device__ __half g_woT [DMODEL * 2 * DMODEL];
__device__ __half g_w1T [DFFN * 2 * DMODEL];
__device__ __half g_w2T [DMODEL * 2 * DFFN];
__device__ float  g_bqkv[NQKV];                      // fused QKV bias

// ---------------- helpers ----------------
__device__ __forceinline__ uint32_t smem_u32(const void* p) {
    uint32_t a;
    asm("{ .reg .u64 t; cvta.to.shared.u64 t, %1; cvt.u32.u64 %0, t; }" : "=r"(a) : "l"(p));
    return a;
}
__device__ __forceinline__ void split_h(float v, __half& h, __half& l) {
    h = __float2half(v);
    l = __float2half(v - __half2float(h));
}
__device__ __forceinline__ void mma16816(float* c, uint32_t a0, uint32_t a1, uint32_t a2,
                                         uint32_t a3, uint32_t b0, uint32_t b1) {
    asm volatile(
        "mma.sync.aligned.m16n8k16.row.col.f32.f16.f16.f32 "
        "{%0,%1,%2,%3}, {%4,%5,%6,%7}, {%8,%9}, {%0,%1,%2,%3};"
        : "+f"(c[0]), "+f"(c[1]), "+f"(c[2]), "+f"(c[3])
        : "r"(a0), "r"(a1), "r"(a2), "r"(a3), "r"(b0), "r"(b1));
}
#define LDM4(r, addr)                                                      \
    asm volatile("ldmatrix.sync.aligned.m8n8.x4.shared.b16 {%0,%1,%2,%3}, [%4];" \
                 : "=r"((r)[0]), "=r"((r)[1]), "=r"((r)[2]), "=r"((r)[3]) : "r"(addr))
#define CP16(dst, src) \
    asm volatile("cp.async.cg.shared.global [%0], [%1], 16;" :: "r"(dst), "l"(src))
#define CP_COMMIT() asm volatile("cp.async.commit_group;" ::: "memory")
#define CP_WAIT2()  asm volatile("cp.async.wait_group 2;" ::: "memory")

// ---------------- fp16-x2 tensor-core GEMM ----------------
// C[M,N] = A[M,K] @ W[K,N] via BT[N][plane][K] (B hi plane only).
// BM=128, BN=128, BK=32, 256 thr, 8 warps of 64x32 (2x4), 3-stage cp.async, 2 CTAs/SM.
// smem stage: [A_hi 8K][A_lo 8K][B_hi 8K] = 24K; rows 64B, chunk' = chunk^((row>>1)&3)
#define STG   24576
#define GSMEM (3 * STG)   // 73728

__global__ void __launch_bounds__(256, 2) gemm_h2_kernel(const __half* __restrict__ A,
                                                         const __half* __restrict__ BT,
                                                         const float* __restrict__ bias,
                                                         const float* __restrict__ resid,
                                                         float* __restrict__ C,
                                                         __half* __restrict__ Cp,
                                                         int K, int N, int relu) {
    extern __shared__ char smem[];
    uint32_t sbase = smem_u32(smem);
    int tid  = threadIdx.x;
    int brow = blockIdx.y * 128;
    int bcol = blockIdx.x * 128;

    int w = tid >> 5, lane = tid & 31;
    int g = lane >> 2, tg = lane & 3;
    int wm = (w >> 2) * 64;          // 0 or 64
    int wn = (w & 3) * 32;           // 0,32,64,96

    // ldmatrix lane geometry (validated R4..R10)
    int rlA  = (lane & 7) + ((lane >> 3) & 1) * 8;
    int kbA  = (lane >> 4) & 1;
    int selA = (rlA >> 1) & 3;
    int rlB  = (lane & 7) + ((lane >> 4) & 1) * 8;
    int kbB  = (lane >> 3) & 1;
    int selB = (rlB >> 1) & 3;

    // fetch: tid<128 -> A row fr (both planes, 4 chunks each);
    //        tid>=128 -> B hi row fr (4 chunks)
    const __half* gA0 = A;
    const __half* gA1 = A;
    const __half* gB_ = BT;
    uint32_t fdst = 0, fx = 0;
    if (tid < 128) {
        int fr = tid;
        gA0 = A + ((size_t)(brow + fr) * 2 + 0) * K;
        gA1 = A + ((size_t)(brow + fr) * 2 + 1) * K;
        fdst = (uint32_t)fr * 64u;
        fx   = (uint32_t)((fr >> 1) & 3);
    } else {
        int fr = tid - 128;
        gB_ = BT + ((size_t)(bcol + fr) * 2) * K;
        fdst = 16384u + (uint32_t)fr * 64u;
        fx   = (uint32_t)((fr >> 1) & 3);
    }
    int nch = K >> 5;

#define FETCH(stage, kc) do {                                                   \
    uint32_t d_ = sbase + (stage) * STG + fdst;                                 \
    if (tid < 128) {                                                            \
        const __half* a0_ = gA0 + (size_t)(kc) * 32;                            \
        const __half* a1_ = gA1 + (size_t)(kc) * 32;                            \
        CP16(d_ + ((0u ^ fx) << 4), a0_ + 0);                                   \
        CP16(d_ + ((1u ^ fx) << 4), a0_ + 8);                                   \
        CP16(d_ + ((2u ^ fx) << 4), a0_ + 16);                                  \
        CP16(d_ + ((3u ^ fx) << 4), a0_ + 24);                                  \
        CP16(d_ + 8192u + ((0u ^ fx) << 4), a1_ + 0);                           \
        CP16(d_ + 8192u + ((1u ^ fx) << 4), a1_ + 8);                           \
        CP16(d_ + 8192u + ((2u ^ fx) << 4), a1_ + 16);                          \
        CP16(d_ + 8192u + ((3u ^ fx) << 4), a1_ + 24);                          \
    } else {                                                                    \
        const __half* b_ = gB_ + (size_t)(kc) * 32;                             \
        CP16(d_ + ((0u ^ fx) << 4), b_ + 0);                                    \
        CP16(d_ + ((1u ^ fx) << 4), b_ + 8);                                    \
        CP16(d_ + ((2u ^ fx) << 4), b_ + 16);                                   \
        CP16(d_ + ((3u ^ fx) << 4), b_ + 24);                                   \
    }                                                                           \
} while (0)

    float acc[4][4][4];
#pragma unroll
    for (int mt = 0; mt < 4; mt++)
#pragma unroll
        for (int nt = 0; nt < 4; nt++)
#pragma unroll
            for (int j = 0; j < 4; j++) acc[mt][nt][j] = 0.f;

    FETCH(0, 0); CP_COMMIT();
    FETCH(1, 1); CP_COMMIT();

    int stage = 0;
    for (int c = 0; c < nch; c++) {
        int fs = c + 2;
        if (fs < nch) { int st = fs - (fs / 3) * 3; FETCH(st, fs); }
        CP_COMMIT();
        CP_WAIT2();
        __syncthreads();

        uint32_t sa = sbase + stage * STG;
#pragma unroll
        for (int h = 0; h < 2; h++) {
            uint32_t ah[4][4], al[4][4];
            uint32_t cA = (uint32_t)(((h * 2 + kbA) ^ selA) << 4);
#pragma unroll
            for (int mt = 0; mt < 4; mt++) {
                uint32_t base = sa + (uint32_t)((wm + mt * 16 + rlA) * 64) + cA;
                LDM4(ah[mt], base);
                LDM4(al[mt], base + 8192);
            }
            uint32_t cB = (uint32_t)(((h * 2 + kbB) ^ selB) << 4);
#pragma unroll
            for (int np = 0; np < 2; np++) {
                uint32_t bh[4];
                LDM4(bh, sa + 16384u + (uint32_t)((wn + np * 16 + rlB) * 64) + cB);
#pragma unroll
                for (int q = 0; q < 2; q++) {
                    int nt = np * 2 + q;
#pragma unroll
                    for (int mt = 0; mt < 4; mt++) {
                        mma16816(acc[mt][nt], ah[mt][0], ah[mt][1], ah[mt][2], ah[mt][3],
                                 bh[q * 2], bh[q * 2 + 1]);
                        mma16816(acc[mt][nt], al[mt][0], al[mt][1], al[mt][2], al[mt][3],
                                 bh[q * 2], bh[q * 2 + 1]);
                    }
                }
            }
        }
        __syncthreads();
        stage++; if (stage == 3) stage = 0;
    }

    // epilogue
#pragma unroll
    for (int mt = 0; mt < 4; mt++) {
#pragma unroll
        for (int half = 0; half < 2; half++) {
            int r = brow + wm + mt * 16 + g + half * 8;
#pragma unroll
            for (int nt = 0; nt < 4; nt++) {
                int col = bcol + wn + nt * 8 + tg * 2;
                float v0 = acc[mt][nt][half * 2 + 0] + __ldg(&bias[col + 0]);
                float v1 = acc[mt][nt][half * 2 + 1] + __ldg(&bias[col + 1]);
                if (relu) { v0 = fmaxf(v0, 0.f); v1 = fmaxf(v1, 0.f); }
                size_t off = (size_t)r * N + col;
                if (resid) {
                    float2 rv = *(const float2*)(resid + off);
                    v0 += rv.x; v1 += rv.y;
                }
                if (Cp) {
                    __half h0, l0, h1, l1;
                    split_h(v0, h0, l0);
                    split_h(v1, h1, l1);
                    __half2 hv; hv.x = h0; hv.y = h1;
                    __half2 lv; lv.x = l0; lv.y = l1;
                    *(__half2*)(Cp + ((size_t)r * 2) * N + col)     = hv;
                    *(__half2*)(Cp + ((size_t)r * 2 + 1) * N + col) = lv;
                } else {
                    float2 fv; fv.x = v0; fv.y = v1;
                    *(float2*)(C + off) = fv;
                }
            }
        }
    }
}

// ---------------- weight transpose + split: out[n][plane][k] from in[k][n] ----------------
__global__ void __launch_bounds__(256) transpose_pack_kernel(const float* __restrict__ in,
                                                             __half* __restrict__ out,
                                                             int R, int Ccols) {
    __shared__ float t[32][33];
    int bx = blockIdx.x * 32, by = blockIdx.y * 32;
    int x = threadIdx.x & 31, y = threadIdx.x >> 5;
#pragma unroll
    for (int j = 0; j < 32; j += 8)
        t[y + j][x] = in[(size_t)(by + y + j) * Ccols + bx + x];
    __syncthreads();
#pragma unroll
    for (int j = 0; j < 32; j += 8) {
        __half h, l;
        split_h(t[x][y + j], h, l);
        size_t nrow = (size_t)(bx + y + j) * 2;
        out[nrow * R + by + x]       = h;
        out[(nrow + 1) * R + by + x] = l;
    }
}

// fused Q/K/V transpose: z selects source; writes into concat wqkvT at n offset z*768
__global__ void __launch_bounds__(256) transpose_qkv_kernel(const float* __restrict__ Wq,
                                                            const float* __restrict__ Wk,
                                                            const float* __restrict__ Wv,
                                                            __half* __restrict__ out) {
    const float* in = (blockIdx.z == 0) ? Wq : (blockIdx.z == 1) ? Wk : Wv;
    __half* dst = out + (size_t)blockIdx.z * DMODEL * 2 * DMODEL;
    __shared__ float t[32][33];
    int bx = blockIdx.x * 32, by = blockIdx.y * 32;
    int x = threadIdx.x & 31, y = threadIdx.x >> 5;
#pragma unroll
    for (int j = 0; j < 32; j += 8)
        t[y + j][x] = in[(size_t)(by + y + j) * DMODEL + bx + x];
    __syncthreads();
#pragma unroll
    for (int j = 0; j < 32; j += 8) {
        __half h, l;
        split_h(t[x][y + j], h, l);
        size_t nrow = (size_t)(bx + y + j) * 2;
        dst[nrow * DMODEL + by + x]       = h;
        dst[(nrow + 1) * DMODEL + by + x] = l;
    }
}

// ---------------- fused QKV bias concat ----------------
__global__ void bias_concat_kernel(const float* __restrict__ bq,
                                   const float* __restrict__ bk,
                                   const float* __restrict__ bv,
                                   float* __restrict__ bqkv) {
    int t = blockIdx.x * 256 + threadIdx.x;
    if (t < DMODEL)            bqkv[t] = bq[t];
    else if (t < 2 * DMODEL)   bqkv[t] = bk[t - DMODEL];
    else if (t < 3 * DMODEL)   bqkv[t] = bv[t - 2 * DMODEL];
}

// ---------------- LayerNorm -> fp16 planes ----------------
__global__ void __launch_bounds__(256) ln_pack_kernel(const float* __restrict__ x,
                                                      const float* __restrict__ gam,
                                                      const float* __restrict__ bet,
                                                      __half* __restrict__ out) {
    int row = blockIdx.x;
    const float* xr = x + (size_t)row * DMODEL;
    int t = threadIdx.x;
    float v0 = xr[t], v1 = xr[t + 256], v2 = xr[t + 512];
    float s  = v0 + v1 + v2;
    float sq = v0 * v0 + v1 * v1 + v2 * v2;
#pragma unroll
    for (int o = 16; o; o >>= 1) {
        s  += __shfl_xor_sync(0xffffffffu, s, o);
        sq += __shfl_xor_sync(0xffffffffu, sq, o);
    }
    __shared__ float rs_[8], rq_[8];
    if ((t & 31) == 0) { rs_[t >> 5] = s; rq_[t >> 5] = sq; }
    __syncthreads();
    s = 0.f; sq = 0.f;
#pragma unroll
    for (int ww = 0; ww < 8; ww++) { s += rs_[ww]; sq += rq_[ww]; }
    float m   = s * (1.f / DMODEL);
    float var = sq * (1.f / DMODEL) - m * m;
    float inv = rsqrtf(var + 1e-5f);
    __half* hiR = out + (size_t)row * 2 * DMODEL;
    __half* loR = hiR + DMODEL;
    __half h, l;
    split_h((v0 - m) * inv * gam[t] + bet[t], h, l);
    hiR[t] = h; loR[t] = l;
    split_h((v1 - m) * inv * gam[t + 256] + bet[t + 256], h, l);
    hiR[t + 256] = h; loR[t + 256] = l;
    split_h((v2 - m) * inv * gam[t + 512] + bet[t + 512], h, l);
    hiR[t + 512] = h; loR[t + 512] = l;
}

// ---------------- BigBird block attention (fused-QKV f32 in, fp16 planes out) ----------------
#define QS  97
#define KTS 68
#define VS  97
#define SCS 324
#define OFF_Q   0
#define OFF_KV  (64 * QS)
#define OFF_SC  (OFF_KV + 96 * KTS)
#define OFF_INV (OFF_SC + 64 * SCS)
#define ATTN_SMEM_BYTES ((OFF_INV + 64) * 4)

__global__ void __launch_bounds__(256) attn_kernel(const float* __restrict__ QKV,
                                                   const int* __restrict__ kb_idx,
                                                   __half* __restrict__ ctxP) {
    extern __shared__ float sm[];
    float* q_s  = sm + OFF_Q;
    float* kv   = sm + OFF_KV;
    float* sc   = sm + OFF_SC;
    float* rinv = sm + OFF_INV;

    int i  = blockIdx.x;
    int hh = blockIdx.y;
    int b  = blockIdx.z;
    int tid = threadIdx.x;
    int base = b * SEQ + i * BLKS;
    const float scale = rsqrtf((float)HDIM);
    const float* Q = QKV;
    const float* K = QKV + DMODEL;
    const float* V = QKV + 2 * DMODEL;

    for (int idx = tid; idx < BLKS * HDIM; idx += 256) {
        int qq = idx / HDIM, d = idx % HDIM;
        q_s[qq * QS + d] = Q[(size_t)(base + qq) * NQKV + hh * HDIM + d] * scale;
    }

    int  kbv[NKBS];
    bool val[NKBS], dia[NKBS];
#pragma unroll
    for (int s = 0; s < NKBS; s++) {
        kbv[s] = kb_idx[i * NKBS + s];
        val[s] = (s == 0) || (kbv[s] != 0);
        dia[s] = (kbv[s] == i);
    }

    int sq0 = (tid >> 4) * 4;
    int sp0 = (tid & 15) * 4;
    __syncthreads();

    for (int s = 0; s < NKBS; s++) {
        if (val[s]) {
            __syncthreads();
            int kbase = b * SEQ + kbv[s] * BLKS;
            for (int idx = tid; idx < BLKS * HDIM; idx += 256) {
                int p = idx / HDIM, d = idx % HDIM;
                kv[d * KTS + p] = K[(size_t)(kbase + p) * NQKV + hh * HDIM + d];
            }
            __syncthreads();
            float acc00=0,acc01=0,acc02=0,acc03=0;
            float acc10=0,acc11=0,acc12=0,acc13=0;
            float acc20=0,acc21=0,acc22=0,acc23=0;
            float acc30=0,acc31=0,acc32=0,acc33=0;
#pragma unroll 4
            for (int d = 0; d < HDIM; d++) {
                float4 bv = *(const float4*)&kv[d * KTS + sp0];
                float a0 = q_s[(sq0 + 0) * QS + d];
                float a1 = q_s[(sq0 + 1) * QS + d];
                float a2 = q_s[(sq0 + 2) * QS + d];
                float a3 = q_s[(sq0 + 3) * QS + d];
                acc00 += a0*bv.x; acc01 += a0*bv.y; acc02 += a0*bv.z; acc03 += a0*bv.w;
                acc10 += a1*bv.x; acc11 += a1*bv.y; acc12 += a1*bv.z; acc13 += a1*bv.w;
                acc20 += a2*bv.x; acc21 += a2*bv.y; acc22 += a2*bv.z; acc23 += a2*bv.w;
                acc30 += a3*bv.x; acc31 += a3*bv.y; acc32 += a3*bv.z; acc33 += a3*bv.w;
            }
            bool dg = dia[s];
            float r[4][4] = {{acc00,acc01,acc02,acc03},{acc10,acc11,acc12,acc13},
                             {acc20,acc21,acc22,acc23},{acc30,acc31,acc32,acc33}};
#pragma unroll
            for (int a = 0; a < 4; a++)
#pragma unroll
                for (int c = 0; c < 4; c++) {
                    int qq = sq0 + a, p = sp0 + c;
                    float v = r[a][c];
                    if (dg && p > qq) v = -1e9f;
                    sc[qq * SCS + s * BLKS + p] = v;
                }
        } else {
            for (int idx = tid; idx < BLKS * BLKS; idx += 256) {
                int qq = idx >> 6, p = idx & 63;
                sc[qq * SCS + s * BLKS + p] = -1e9f;
            }
        }
    }
    __syncthreads();

    {
        int qq = tid >> 2, l4 = tid & 3;
        float* row = sc + qq * SCS;
        float m = -1e30f;
        for (int idx = l4; idx < NKBS * BLKS; idx += 4) m = fmaxf(m, row[idx]);
        m = fmaxf(m, __shfl_xor_sync(0xffffffffu, m, 1));
        m = fmaxf(m, __shfl_xor_sync(0xffffffffu, m, 2));
        float ss = 0.f;
        for (int idx = l4; idx < NKBS * BLKS; idx += 4) {
            float e = __expf(row[idx] - m);
            row[idx] = e;
            ss += e;
        }
        ss += __shfl_xor_sync(0xffffffffu, ss, 1);
        ss += __shfl_xor_sync(0xffffffffu, ss, 2);
        if (l4 == 0) rinv[qq] = 1.f / ss;
    }
    __syncthreads();

    int cq0 = (tid >> 4) * 4;
    int cd0 = (tid & 15) * 6;
    float cacc[4][6];
#pragma unroll
    for (int a = 0; a < 4; a++)
#pragma unroll
        for (int k = 0; k < 6; k++) cacc[a][k] = 0.f;

    for (int s = 0; s < NKBS; s++) {
        if (!val[s]) continue;
        __syncthreads();
        int kbase = b * SEQ + kbv[s] * BLKS;
        for (int idx = tid; idx < BLKS * HDIM; idx += 256) {
            int p = idx / HDIM, d = idx % HDIM;
            kv[p * VS + d] = V[(size_t)(kbase + p) * NQKV + hh * HDIM + d];
        }
        __syncthreads();
#pragma unroll 2
        for (int p = 0; p < BLKS; p++) {
            float pr0 = sc[(cq0 + 0) * SCS + s * BLKS + p];
            float pr1 = sc[(cq0 + 1) * SCS + s * BLKS + p];
            float pr2 = sc[(cq0 + 2) * SCS + s * BLKS + p];
            float pr3 = sc[(cq0 + 3) * SCS + s * BLKS + p];
            const float* vp = &kv[p * VS + cd0];
#pragma unroll
            for (int k = 0; k < 6; k++) {
                float vv = vp[k];
                cacc[0][k] += pr0 * vv;
                cacc[1][k] += pr1 * vv;
                cacc[2][k] += pr2 * vv;
                cacc[3][k] += pr3 * vv;
            }
        }
    }

#pragma unroll
    for (int a = 0; a < 4; a++) {
        float rv = rinv[cq0 + a];
        size_t hiOff = ((size_t)(base + cq0 + a) * 2) * DMODEL + hh * HDIM + cd0;
#pragma unroll
        for (int k = 0; k < 6; k++) {
            __half h, l;
            split_h(cacc[a][k] * rv, h, l);
            ctxP[hiOff + k]          = h;
            ctxP[hiOff + DMODEL + k] = l;
        }
    }
}

// ---------------- host launcher ----------------
extern "C" void kernel_launch(void* const* d_in, const int* in_sizes, int n_in,
                              void* d_out, int out_size) {
    const float* x    = (const float*)d_in[0];
    const float* Wq   = (const float*)d_in[1];
    const float* bq   = (const float*)d_in[2];
    const float* Wk   = (const float*)d_in[3];
    const float* bk   = (const float*)d_in[4];
    const float* Wv   = (const float*)d_in[5];
    const float* bv   = (const float*)d_in[6];
    const float* Wo   = (const float*)d_in[7];
    const float* bo   = (const float*)d_in[8];
    const float* ln_g = (const float*)d_in[9];
    const float* ln_b = (const float*)d_in[10];
    const float* W1   = (const float*)d_in[11];
    const float* b1   = (const float*)d_in[12];
    const float* W2   = (const float*)d_in[13];
    const float* b2   = (const float*)d_in[14];
    const int*   kb   = (const int*)d_in[15];
    float* out = (float*)d_out;

    __half *phP, *pctxP, *pffnP, *wqkvT, *woT, *w1T, *w2T;
    float *pqkv, *px, *pbqkv;
    cudaGetSymbolAddress((void**)&phP,   g_hP);
    cudaGetSymbolAddress((void**)&pctxP, g_ctxP);
    cudaGetSymbolAddress((void**)&pffnP, g_ffnP);
    cudaGetSymbolAddress((void**)&pqkv,  g_qkv);
    cudaGetSymbolAddress((void**)&px,    g_x);
    cudaGetSymbolAddress((void**)&wqkvT, g_wqkvT);
    cudaGetSymbolAddress((void**)&woT,   g_woT);
    cudaGetSymbolAddress((void**)&w1T,   g_w1T);
    cudaGetSymbolAddress((void**)&w2T,   g_w2T);
    cudaGetSymbolAddress((void**)&pbqkv, g_bqkv);

    cudaFuncSetAttribute(attn_kernel, cudaFuncAttributeMaxDynamicSharedMemorySize,
                         ATTN_SMEM_BYTES);
    cudaFuncSetAttribute(gemm_h2_kernel, cudaFuncAttributeMaxDynamicSharedMemorySize,
                         GSMEM);

    dim3 tDD(DMODEL / 32, DMODEL / 32);
    dim3 gQKV(NQKV / 128, TOKENS / 128);   // (18,128)
    dim3 gWo (DMODEL / 128, TOKENS / 128); // (6,128)
    dim3 gF1 (DFFN / 128, TOKENS / 128);   // (24,128)

    // ncu -s 5 with 2 harness-injected launches samples OUR kernel index 3 = QKV GEMM
    ln_pack_kernel<<<TOKENS, 256>>>(x, ln_g, ln_b, phP);                           // 0
    transpose_qkv_kernel<<<dim3(DMODEL / 32, DMODEL / 32, 3), 256>>>(Wq, Wk, Wv,   // 1
                                                                     wqkvT);
    bias_concat_kernel<<<(NQKV + 255) / 256, 256>>>(bq, bk, bv, pbqkv);            // 2
    gemm_h2_kernel<<<gQKV, 256, GSMEM>>>(phP, wqkvT, pbqkv, nullptr, pqkv,         // 3 <- ncu
                                         nullptr, DMODEL, NQKV, 0);
    transpose_pack_kernel<<<tDD, 256>>>(Wo, woT, DMODEL, DMODEL);                  // 4
    attn_kernel<<<dim3(NBLK, NHEAD, BATCH), 256, ATTN_SMEM_BYTES>>>(pqkv, kb,      // 5
                                                                    pctxP);
    gemm_h2_kernel<<<gWo, 256, GSMEM>>>(pctxP, woT, bo, x, px, nullptr,            // 6
                                        DMODEL, DMODEL, 0);
    ln_pack_kernel<<<TOKENS, 256>>>(px, ln_g, ln_b, phP);                          // 7
    transpose_pack_kernel<<<dim3(DFFN / 32, DMODEL / 32), 256>>>(W1, w1T,          // 8
                                                                 DMODEL, DFFN);
    transpose_pack_kernel<<<dim3(DMODEL / 32, DFFN / 32), 256>>>(W2, w2T,          // 9
                                                                 DFFN, DMODEL);
    gemm_h2_kernel<<<gF1, 256, GSMEM>>>(phP, w1T, b1, nullptr, nullptr, pffnP,     // 10
                                        DMODEL, DFFN, 1);
    gemm_h2_kernel<<<gWo, 256, GSMEM>>>(pffnP, w2T, b2, px, out, nullptr,          // 11
                                        DFFN, DMODEL, 0);
}

// round 12
// speedup vs baseline: 1.4285x; 1.3366x over previous
#include <cuda_runtime.h>
#include <cuda_fp16.h>
#include <cstdint>

#define TOKENS 16384
#define DMODEL 768
#define DFFN   3072
#define NQKV   2304
#define NHEAD  8
#define HDIM   96
#define NBLK   64
#define BLKS   64
#define NKBS   5
#define SEQ    4096
#define BATCH  4

// ---------------- scratch (static device globals; no allocation) ----------------
__device__ __half g_hP  [TOKENS * DMODEL];           // fp16 single plane
__device__ __half g_ctxP[TOKENS * DMODEL];
__device__ __half g_ffnP[(size_t)TOKENS * DFFN];
__device__ float  g_qkv [(size_t)TOKENS * NQKV];     // fused Q|K|V, row stride 2304
__device__ float  g_x   [TOKENS * DMODEL];
__device__ __half g_wqkvT[NQKV * DMODEL];            // [n][k], n = q|k|v concat
__device__ __half g_woT [DMODEL * DMODEL];
__device__ __half g_w1T [DFFN * DMODEL];
__device__ __half g_w2T [DMODEL * DFFN];
__device__ float  g_bqkv[NQKV];                      // fused QKV bias

// ---------------- helpers ----------------
__device__ __forceinline__ uint32_t smem_u32(const void* p) {
    uint32_t a;
    asm("{ .reg .u64 t; cvta.to.shared.u64 t, %1; cvt.u32.u64 %0, t; }" : "=r"(a) : "l"(p));
    return a;
}
__device__ __forceinline__ void mma16816(float* c, uint32_t a0, uint32_t a1, uint32_t a2,
                                         uint32_t a3, uint32_t b0, uint32_t b1) {
    asm volatile(
        "mma.sync.aligned.m16n8k16.row.col.f32.f16.f16.f32 "
        "{%0,%1,%2,%3}, {%4,%5,%6,%7}, {%8,%9}, {%0,%1,%2,%3};"
        : "+f"(c[0]), "+f"(c[1]), "+f"(c[2]), "+f"(c[3])
        : "r"(a0), "r"(a1), "r"(a2), "r"(a3), "r"(b0), "r"(b1));
}
#define LDM4(r, addr)                                                      \
    asm volatile("ldmatrix.sync.aligned.m8n8.x4.shared.b16 {%0,%1,%2,%3}, [%4];" \
                 : "=r"((r)[0]), "=r"((r)[1]), "=r"((r)[2]), "=r"((r)[3]) : "r"(addr))
#define CP16(dst, src) \
    asm volatile("cp.async.cg.shared.global [%0], [%1], 16;" :: "r"(dst), "l"(src))
#define CP_COMMIT() asm volatile("cp.async.commit_group;" ::: "memory")
#define CP_WAIT2()  asm volatile("cp.async.wait_group 2;" ::: "memory")

// ---------------- single-pass fp16 tensor-core GEMM ----------------
// C[M,N] = A[M,K] @ W[K,N] via BT[N][K], both pure fp16.
// BM=128, BN=128, BK=32, 256 thr, 8 warps of 64x32 (2x4), 3-stage cp.async, 2 CTAs/SM.
// smem stage: [A 8K][B 8K] = 16K; rows 64B, chunk' = chunk^((row>>1)&3)
#define STG   16384
#define GSMEM (3 * STG)   // 49152

__global__ void __launch_bounds__(256, 2) gemm_h1_kernel(const __half* __restrict__ A,
                                                         const __half* __restrict__ BT,
                                                         const float* __restrict__ bias,
                                                         const float* __restrict__ resid,
                                                         float* __restrict__ C,
                                                         __half* __restrict__ Cp,
                                                         int K, int N, int relu) {
    extern __shared__ char smem[];
    uint32_t sbase = smem_u32(smem);
    int tid  = threadIdx.x;
    int brow = blockIdx.y * 128;
    int bcol = blockIdx.x * 128;

    int w = tid >> 5, lane = tid & 31;
    int g = lane >> 2, tg = lane & 3;
    int wm = (w >> 2) * 64;          // 0 or 64
    int wn = (w & 3) * 32;           // 0,32,64,96

    // ldmatrix lane geometry (validated R4..R11)
    int rlA  = (lane & 7) + ((lane >> 3) & 1) * 8;
    int kbA  = (lane >> 4) & 1;
    int selA = (rlA >> 1) & 3;
    int rlB  = (lane & 7) + ((lane >> 4) & 1) * 8;
    int kbB  = (lane >> 3) & 1;
    int selB = (rlB >> 1) & 3;

    // fetch: tid<128 -> A row fr (4 chunks); tid>=128 -> B row fr (4 chunks)
    const __half* gsrc;
    uint32_t fdst, fx;
    if (tid < 128) {
        int fr = tid;
        gsrc = A + (size_t)(brow + fr) * K;
        fdst = (uint32_t)fr * 64u;
        fx   = (uint32_t)((fr >> 1) & 3);
    } else {
        int fr = tid - 128;
        gsrc = BT + (size_t)(bcol + fr) * K;
        fdst = 8192u + (uint32_t)fr * 64u;
        fx   = (uint32_t)((fr >> 1) & 3);
    }
    int nch = K >> 5;

#define FETCH(stage, kc) do {                                                   \
    uint32_t d_ = sbase + (stage) * STG + fdst;                                 \
    const __half* s_ = gsrc + (size_t)(kc) * 32;                                \
    CP16(d_ + ((0u ^ fx) << 4), s_ + 0);                                        \
    CP16(d_ + ((1u ^ fx) << 4), s_ + 8);                                        \
    CP16(d_ + ((2u ^ fx) << 4), s_ + 16);                                       \
    CP16(d_ + ((3u ^ fx) << 4), s_ + 24);                                       \
} while (0)

    float acc[4][4][4];
#pragma unroll
    for (int mt = 0; mt < 4; mt++)
#pragma unroll
        for (int nt = 0; nt < 4; nt++)
#pragma unroll
            for (int j = 0; j < 4; j++) acc[mt][nt][j] = 0.f;

    FETCH(0, 0); CP_COMMIT();
    FETCH(1, 1); CP_COMMIT();

    int stage = 0;
    for (int c = 0; c < nch; c++) {
        int fs = c + 2;
        if (fs < nch) { int st = fs - (fs / 3) * 3; FETCH(st, fs); }
        CP_COMMIT();
        CP_WAIT2();
        __syncthreads();

        uint32_t sa = sbase + stage * STG;
#pragma unroll
        for (int h = 0; h < 2; h++) {
            uint32_t ah[4][4];
            uint32_t cA = (uint32_t)(((h * 2 + kbA) ^ selA) << 4);
#pragma unroll
            for (int mt = 0; mt < 4; mt++)
                LDM4(ah[mt], sa + (uint32_t)((wm + mt * 16 + rlA) * 64) + cA);
            uint32_t cB = (uint32_t)(((h * 2 + kbB) ^ selB) << 4);
#pragma unroll
            for (int np = 0; np < 2; np++) {
                uint32_t bh[4];
                LDM4(bh, sa + 8192u + (uint32_t)((wn + np * 16 + rlB) * 64) + cB);
#pragma unroll
                for (int q = 0; q < 2; q++) {
                    int nt = np * 2 + q;
#pragma unroll
                    for (int mt = 0; mt < 4; mt++)
                        mma16816(acc[mt][nt], ah[mt][0], ah[mt][1], ah[mt][2], ah[mt][3],
                                 bh[q * 2], bh[q * 2 + 1]);
                }
            }
        }
        __syncthreads();
        stage++; if (stage == 3) stage = 0;
    }

    // epilogue
#pragma unroll
    for (int mt = 0; mt < 4; mt++) {
#pragma unroll
        for (int half = 0; half < 2; half++) {
            int r = brow + wm + mt * 16 + g + half * 8;
#pragma unroll
            for (int nt = 0; nt < 4; nt++) {
                int col = bcol + wn + nt * 8 + tg * 2;
                float v0 = acc[mt][nt][half * 2 + 0] + __ldg(&bias[col + 0]);
                float v1 = acc[mt][nt][half * 2 + 1] + __ldg(&bias[col + 1]);
                if (relu) { v0 = fmaxf(v0, 0.f); v1 = fmaxf(v1, 0.f); }
                size_t off = (size_t)r * N + col;
                if (resid) {
                    float2 rv = *(const float2*)(resid + off);
                    v0 += rv.x; v1 += rv.y;
                }
                if (Cp) {
                    __half2 hv;
                    hv.x = __float2half(v0);
                    hv.y = __float2half(v1);
                    *(__half2*)(Cp + off) = hv;
                } else {
                    float2 fv; fv.x = v0; fv.y = v1;
                    *(float2*)(C + off) = fv;
                }
            }
        }
    }
}

// ---------------- weight transpose: out[n][k] = fp16(in[k][n]) ----------------
__global__ void __launch_bounds__(256) transpose_pack_kernel(const float* __restrict__ in,
                                                             __half* __restrict__ out,
                                                             int R, int Ccols) {
    __shared__ float t[32][33];
    int bx = blockIdx.x * 32, by = blockIdx.y * 32;
    int x = threadIdx.x & 31, y = threadIdx.x >> 5;
#pragma unroll
    for (int j = 0; j < 32; j += 8)
        t[y + j][x] = in[(size_t)(by + y + j) * Ccols + bx + x];
    __syncthreads();
#pragma unroll
    for (int j = 0; j < 32; j += 8)
        out[(size_t)(bx + y + j) * R + by + x] = __float2half(t[x][y + j]);
}

// fused Q/K/V transpose into concat wqkvT
__global__ void __launch_bounds__(256) transpose_qkv_kernel(const float* __restrict__ Wq,
                                                            const float* __restrict__ Wk,
                                                            const float* __restrict__ Wv,
                                                            __half* __restrict__ out) {
    const float* in = (blockIdx.z == 0) ? Wq : (blockIdx.z == 1) ? Wk : Wv;
    __half* dst = out + (size_t)blockIdx.z * DMODEL * DMODEL;
    __shared__ float t[32][33];
    int bx = blockIdx.x * 32, by = blockIdx.y * 32;
    int x = threadIdx.x & 31, y = threadIdx.x >> 5;
#pragma unroll
    for (int j = 0; j < 32; j += 8)
        t[y + j][x] = in[(size_t)(by + y + j) * DMODEL + bx + x];
    __syncthreads();
#pragma unroll
    for (int j = 0; j < 32; j += 8)
        dst[(size_t)(bx + y + j) * DMODEL + by + x] = __float2half(t[x][y + j]);
}

// ---------------- fused QKV bias concat ----------------
__global__ void bias_concat_kernel(const float* __restrict__ bq,
                                   const float* __restrict__ bk,
                                   const float* __restrict__ bv,
                                   float* __restrict__ bqkv) {
    int t = blockIdx.x * 256 + threadIdx.x;
    if (t < DMODEL)            bqkv[t] = bq[t];
    else if (t < 2 * DMODEL)   bqkv[t] = bk[t - DMODEL];
    else if (t < 3 * DMODEL)   bqkv[t] = bv[t - 2 * DMODEL];
}

// ---------------- LayerNorm -> fp16 ----------------
__global__ void __launch_bounds__(256) ln_pack_kernel(const float* __restrict__ x,
                                                      const float* __restrict__ gam,
                                                      const float* __restrict__ bet,
                                                      __half* __restrict__ out) {
    int row = blockIdx.x;
    const float* xr = x + (size_t)row * DMODEL;
    int t = threadIdx.x;
    float v0 = xr[t], v1 = xr[t + 256], v2 = xr[t + 512];
    float s  = v0 + v1 + v2;
    float sq = v0 * v0 + v1 * v1 + v2 * v2;
#pragma unroll
    for (int o = 16; o; o >>= 1) {
        s  += __shfl_xor_sync(0xffffffffu, s, o);
        sq += __shfl_xor_sync(0xffffffffu, sq, o);
    }
    __shared__ float rs_[8], rq_[8];
    if ((t & 31) == 0) { rs_[t >> 5] = s; rq_[t >> 5] = sq; }
    __syncthreads();
    s = 0.f; sq = 0.f;
#pragma unroll
    for (int ww = 0; ww < 8; ww++) { s += rs_[ww]; sq += rq_[ww]; }
    float m   = s * (1.f / DMODEL);
    float var = sq * (1.f / DMODEL) - m * m;
    float inv = rsqrtf(var + 1e-5f);
    __half* orow = out + (size_t)row * DMODEL;
    orow[t]       = __float2half((v0 - m) * inv * gam[t]       + bet[t]);
    orow[t + 256] = __float2half((v1 - m) * inv * gam[t + 256] + bet[t + 256]);
    orow[t + 512] = __float2half((v2 - m) * inv * gam[t + 512] + bet[t + 512]);
}

// ---------------- BigBird block attention (fused-QKV f32 in, fp16 out) ----------------
#define QS  97
#define KTS 68
#define VS  97
#define SCS 324
#define OFF_Q   0
#define OFF_KV  (64 * QS)
#define OFF_SC  (OFF_KV + 96 * KTS)
#define OFF_INV (OFF_SC + 64 * SCS)
#define ATTN_SMEM_BYTES ((OFF_INV + 64) * 4)

__global__ void __launch_bounds__(256) attn_kernel(const float* __restrict__ QKV,
                                                   const int* __restrict__ kb_idx,
                                                   __half* __restrict__ ctxP) {
    extern __shared__ float sm[];
    float* q_s  = sm + OFF_Q;
    float* kv   = sm + OFF_KV;
    float* sc   = sm + OFF_SC;
    float* rinv = sm + OFF_INV;

    int i  = blockIdx.x;
    int hh = blockIdx.y;
    int b  = blockIdx.z;
    int tid = threadIdx.x;
    int base = b * SEQ + i * BLKS;
    const float scale = rsqrtf((float)HDIM);
    const float* Q = QKV;
    const float* K = QKV + DMODEL;
    const float* V = QKV + 2 * DMODEL;

    for (int idx = tid; idx < BLKS * HDIM; idx += 256) {
        int qq = idx / HDIM, d = idx % HDIM;
        q_s[qq * QS + d] = Q[(size_t)(base + qq) * NQKV + hh * HDIM + d] * scale;
    }

    int  kbv[NKBS];
    bool val[NKBS], dia[NKBS];
#pragma unroll
    for (int s = 0; s < NKBS; s++) {
        kbv[s] = kb_idx[i * NKBS + s];
        val[s] = (s == 0) || (kbv[s] != 0);
        dia[s] = (kbv[s] == i);
    }

    int sq0 = (tid >> 4) * 4;
    int sp0 = (tid & 15) * 4;
    __syncthreads();

    for (int s = 0; s < NKBS; s++) {
        if (val[s]) {
            __syncthreads();
            int kbase = b * SEQ + kbv[s] * BLKS;
            for (int idx = tid; idx < BLKS * HDIM; idx += 256) {
                int p = idx / HDIM, d = idx % HDIM;
                kv[d * KTS + p] = K[(size_t)(kbase + p) * NQKV + hh * HDIM + d];
            }
            __syncthreads();
            float acc00=0,acc01=0,acc02=0,acc03=0;
            float acc10=0,acc11=0,acc12=0,acc13=0;
            float acc20=0,acc21=0,acc22=0,acc23=0;
            float acc30=0,acc31=0,acc32=0,acc33=0;
#pragma unroll 4
            for (int d = 0; d < HDIM; d++) {
                float4 bv = *(const float4*)&kv[d * KTS + sp0];
                float a0 = q_s[(sq0 + 0) * QS + d];
                float a1 = q_s[(sq0 + 1) * QS + d];
                float a2 = q_s[(sq0 + 2) * QS + d];
                float a3 = q_s[(sq0 + 3) * QS + d];
                acc00 += a0*bv.x; acc01 += a0*bv.y; acc02 += a0*bv.z; acc03 += a0*bv.w;
                acc10 += a1*bv.x; acc11 += a1*bv.y; acc12 += a1*bv.z; acc13 += a1*bv.w;
                acc20 += a2*bv.x; acc21 += a2*bv.y; acc22 += a2*bv.z; acc23 += a2*bv.w;
                acc30 += a3*bv.x; acc31 += a3*bv.y; acc32 += a3*bv.z; acc33 += a3*bv.w;
            }
            bool dg = dia[s];
            float r[4][4] = {{acc00,acc01,acc02,acc03},{acc10,acc11,acc12,acc13},
                             {acc20,acc21,acc22,acc23},{acc30,acc31,acc32,acc33}};
#pragma unroll
            for (int a = 0; a < 4; a++)
#pragma unroll
                for (int c = 0; c < 4; c++) {
                    int qq = sq0 + a, p = sp0 + c;
                    float v = r[a][c];
                    if (dg && p > qq) v = -1e9f;
                    sc[qq * SCS + s * BLKS + p] = v;
                }
        } else {
            for (int idx = tid; idx < BLKS * BLKS; idx += 256) {
                int qq = idx >> 6, p = idx & 63;
                sc[qq * SCS + s * BLKS + p] = -1e9f;
            }
        }
    }
    __syncthreads();

    {
        int qq = tid >> 2, l4 = tid & 3;
        float* row = sc + qq * SCS;
        float m = -1e30f;
        for (int idx = l4; idx < NKBS * BLKS; idx += 4) m = fmaxf(m, row[idx]);
        m = fmaxf(m, __shfl_xor_sync(0xffffffffu, m, 1));
        m = fmaxf(m, __shfl_xor_sync(0xffffffffu, m, 2));
        float ss = 0.f;
        for (int idx = l4; idx < NKBS * BLKS; idx += 4) {
            float e = __expf(row[idx] - m);
            row[idx] = e;
            ss += e;
        }
        ss += __shfl_xor_sync(0xffffffffu, ss, 1);
        ss += __shfl_xor_sync(0xffffffffu, ss, 2);
        if (l4 == 0) rinv[qq] = 1.f / ss;
    }
    __syncthreads();

    int cq0 = (tid >> 4) * 4;
    int cd0 = (tid & 15) * 6;
    float cacc[4][6];
#pragma unroll
    for (int a = 0; a < 4; a++)
#pragma unroll
        for (int k = 0; k < 6; k++) cacc[a][k] = 0.f;

    for (int s = 0; s < NKBS; s++) {
        if (!val[s]) continue;
        __syncthreads();
        int kbase = b * SEQ + kbv[s] * BLKS;
        for (int idx = tid; idx < BLKS * HDIM; idx += 256) {
            int p = idx / HDIM, d = idx % HDIM;
            kv[p * VS + d] = V[(size_t)(kbase + p) * NQKV + hh * HDIM + d];
        }
        __syncthreads();
#pragma unroll 2
        for (int p = 0; p < BLKS; p++) {
            float pr0 = sc[(cq0 + 0) * SCS + s * BLKS + p];
            float pr1 = sc[(cq0 + 1) * SCS + s * BLKS + p];
            float pr2 = sc[(cq0 + 2) * SCS + s * BLKS + p];
            float pr3 = sc[(cq0 + 3) * SCS + s * BLKS + p];
            const float* vp = &kv[p * VS + cd0];
#pragma unroll
            for (int k = 0; k < 6; k++) {
                float vv = vp[k];
                cacc[0][k] += pr0 * vv;
                cacc[1][k] += pr1 * vv;
                cacc[2][k] += pr2 * vv;
                cacc[3][k] += pr3 * vv;
            }
        }
    }

#pragma unroll
    for (int a = 0; a < 4; a++) {
        float rv = rinv[cq0 + a];
        size_t off = (size_t)(base + cq0 + a) * DMODEL + hh * HDIM + cd0;
#pragma unroll
        for (int k = 0; k < 6; k++)
            ctxP[off + k] = __float2half(cacc[a][k] * rv);
    }
}

// ---------------- host launcher ----------------
extern "C" void kernel_launch(void* const* d_in, const int* in_sizes, int n_in,
                              void* d_out, int out_size) {
    const float* x    = (const float*)d_in[0];
    const float* Wq   = (const float*)d_in[1];
    const float* bq   = (const float*)d_in[2];
    const float* Wk   = (const float*)d_in[3];
    const float* bk   = (const float*)d_in[4];
    const float* Wv   = (const float*)d_in[5];
    const float* bv   = (const float*)d_in[6];
    const float* Wo   = (const float*)d_in[7];
    const float* bo   = (const float*)d_in[8];
    const float* ln_g = (const float*)d_in[9];
    const float* ln_b = (const float*)d_in[10];
    const float* W1   = (const float*)d_in[11];
    const float* b1   = (const float*)d_in[12];
    const float* W2   = (const float*)d_in[13];
    const float* b2   = (const float*)d_in[14];
    const int*   kb   = (const int*)d_in[15];
    float* out = (float*)d_out;

    __half *phP, *pctxP, *pffnP, *wqkvT, *woT, *w1T, *w2T;
    float *pqkv, *px, *pbqkv;
    cudaGetSymbolAddress((void**)&phP,   g_hP);
    cudaGetSymbolAddress((void**)&pctxP, g_ctxP);
    cudaGetSymbolAddress((void**)&pffnP, g_ffnP);
    cudaGetSymbolAddress((void**)&pqkv,  g_qkv);
    cudaGetSymbolAddress((void**)&px,    g_x);
    cudaGetSymbolAddress((void**)&wqkvT, g_wqkvT);
    cudaGetSymbolAddress((void**)&woT,   g_woT);
    cudaGetSymbolAddress((void**)&w1T,   g_w1T);
    cudaGetSymbolAddress((void**)&w2T,   g_w2T);
    cudaGetSymbolAddress((void**)&pbqkv, g_bqkv);

    cudaFuncSetAttribute(attn_kernel, cudaFuncAttributeMaxDynamicSharedMemorySize,
                         ATTN_SMEM_BYTES);
    cudaFuncSetAttribute(gemm_h1_kernel, cudaFuncAttributeMaxDynamicSharedMemorySize,
                         GSMEM);

    dim3 tDD(DMODEL / 32, DMODEL / 32);
    dim3 gQKV(NQKV / 128, TOKENS / 128);   // (18,128)
    dim3 gWo (DMODEL / 128, TOKENS / 128); // (6,128)
    dim3 gF1 (DFFN / 128, TOKENS / 128);   // (24,128)

    // ncu -s 5 with 2 harness-injected launches samples OUR kernel index 3 = QKV GEMM
    ln_pack_kernel<<<TOKENS, 256>>>(x, ln_g, ln_b, phP);                           // 0
    transpose_qkv_kernel<<<dim3(DMODEL / 32, DMODEL / 32, 3), 256>>>(Wq, Wk, Wv,   // 1
                                                                     wqkvT);
    bias_concat_kernel<<<(NQKV + 255) / 256, 256>>>(bq, bk, bv, pbqkv);            // 2
    gemm_h1_kernel<<<gQKV, 256, GSMEM>>>(phP, wqkvT, pbqkv, nullptr, pqkv,         // 3 <- ncu
                                         nullptr, DMODEL, NQKV, 0);
    transpose_pack_kernel<<<tDD, 256>>>(Wo, woT, DMODEL, DMODEL);                  // 4
    attn_kernel<<<dim3(NBLK, NHEAD, BATCH), 256, ATTN_SMEM_BYTES>>>(pqkv, kb,      // 5
                                                                    pctxP);
    gemm_h1_kernel<<<gWo, 256, GSMEM>>>(pctxP, woT, bo, x, px, nullptr,            // 6
                                        DMODEL, DMODEL, 0);
    ln_pack_kernel<<<TOKENS, 256>>>(px, ln_g, ln_b, phP);                          // 7
    transpose_pack_kernel<<<dim3(DFFN / 32, DMODEL / 32), 256>>>(W1, w1T,          // 8
                                                                 DMODEL, DFFN);
    transpose_pack_kernel<<<dim3(DMODEL / 32, DFFN / 32), 256>>>(W2, w2T,          // 9
                                                                 DFFN, DMODEL);
    gemm_h1_kernel<<<gF1, 256, GSMEM>>>(phP, w1T, b1, nullptr, nullptr, pffnP,     // 10
                                        DMODEL, DFFN, 1);
    gemm_h1_kernel<<<gWo, 256, GSMEM>>>(pffnP, w2T, b2, px, out, nullptr,          // 11
                                        DFFN, DMODEL, 0);
}

// round 13
// speedup vs baseline: 2.1154x; 1.4808x over previous
#include <cuda_runtime.h>
#include <cuda_fp16.h>
#include <cstdint>

#define TOKENS 16384
#define DMODEL 768
#define DFFN   3072
#define NQKV   2304
#define NHEAD  8
#define HDIM   96
#define NBLK   64
#define BLKS   64
#define NKBS   5
#define SEQ    4096
#define BATCH  4

// ---------------- scratch (static device globals; no allocation) ----------------
__device__ __half g_hP  [TOKENS * DMODEL];           // fp16 LN output
__device__ __half g_ctxP[TOKENS * DMODEL];
__device__ __half g_ffnP[(size_t)TOKENS * DFFN];
__device__ __half g_qkvh[(size_t)TOKENS * NQKV];     // fused Q|K|V fp16
__device__ float  g_x   [TOKENS * DMODEL];
__device__ __half g_wqkvT[NQKV * DMODEL];            // [n][k]
__device__ __half g_woT [DMODEL * DMODEL];
__device__ __half g_w1T [DFFN * DMODEL];
__device__ __half g_w2T [DMODEL * DFFN];
__device__ float  g_bqkv[NQKV];

// ---------------- helpers ----------------
__device__ __forceinline__ uint32_t smem_u32(const void* p) {
    uint32_t a;
    asm("{ .reg .u64 t; cvta.to.shared.u64 t, %1; cvt.u32.u64 %0, t; }" : "=r"(a) : "l"(p));
    return a;
}
__device__ __forceinline__ void mma16816(float* c, uint32_t a0, uint32_t a1, uint32_t a2,
                                         uint32_t a3, uint32_t b0, uint32_t b1) {
    asm volatile(
        "mma.sync.aligned.m16n8k16.row.col.f32.f16.f16.f32 "
        "{%0,%1,%2,%3}, {%4,%5,%6,%7}, {%8,%9}, {%0,%1,%2,%3};"
        : "+f"(c[0]), "+f"(c[1]), "+f"(c[2]), "+f"(c[3])
        : "r"(a0), "r"(a1), "r"(a2), "r"(a3), "r"(b0), "r"(b1));
}
#define LDM4(r, addr)                                                      \
    asm volatile("ldmatrix.sync.aligned.m8n8.x4.shared.b16 {%0,%1,%2,%3}, [%4];" \
                 : "=r"((r)[0]), "=r"((r)[1]), "=r"((r)[2]), "=r"((r)[3]) : "r"(addr))
#define LDM4T(r, addr)                                                     \
    asm volatile("ldmatrix.sync.aligned.m8n8.x4.trans.shared.b16 {%0,%1,%2,%3}, [%4];" \
                 : "=r"((r)[0]), "=r"((r)[1]), "=r"((r)[2]), "=r"((r)[3]) : "r"(addr))
#define CP16(dst, src) \
    asm volatile("cp.async.cg.shared.global [%0], [%1], 16;" :: "r"(dst), "l"(src))
#define CP_COMMIT() asm volatile("cp.async.commit_group;" ::: "memory")
#define CP_WAIT2()  asm volatile("cp.async.wait_group 2;" ::: "memory")

// ---------------- single-pass fp16 tensor-core GEMM (unchanged from R12) ----------------
#define STG   16384
#define GSMEM (3 * STG)

__global__ void __launch_bounds__(256, 2) gemm_h1_kernel(const __half* __restrict__ A,
                                                         const __half* __restrict__ BT,
                                                         const float* __restrict__ bias,
                                                         const float* __restrict__ resid,
                                                         float* __restrict__ C,
                                                         __half* __restrict__ Cp,
                                                         int K, int N, int relu) {
    extern __shared__ char smem[];
    uint32_t sbase = smem_u32(smem);
    int tid  = threadIdx.x;
    int brow = blockIdx.y * 128;
    int bcol = blockIdx.x * 128;

    int w = tid >> 5, lane = tid & 31;
    int g = lane >> 2, tg = lane & 3;
    int wm = (w >> 2) * 64;
    int wn = (w & 3) * 32;

    int rlA  = (lane & 7) + ((lane >> 3) & 1) * 8;
    int kbA  = (lane >> 4) & 1;
    int selA = (rlA >> 1) & 3;
    int rlB  = (lane & 7) + ((lane >> 4) & 1) * 8;
    int kbB  = (lane >> 3) & 1;
    int selB = (rlB >> 1) & 3;

    const __half* gsrc;
    uint32_t fdst, fx;
    if (tid < 128) {
        int fr = tid;
        gsrc = A + (size_t)(brow + fr) * K;
        fdst = (uint32_t)fr * 64u;
        fx   = (uint32_t)((fr >> 1) & 3);
    } else {
        int fr = tid - 128;
        gsrc = BT + (size_t)(bcol + fr) * K;
        fdst = 8192u + (uint32_t)fr * 64u;
        fx   = (uint32_t)((fr >> 1) & 3);
    }
    int nch = K >> 5;

#define FETCH(stage, kc) do {                                                   \
    uint32_t d_ = sbase + (stage) * STG + fdst;                                 \
    const __half* s_ = gsrc + (size_t)(kc) * 32;                                \
    CP16(d_ + ((0u ^ fx) << 4), s_ + 0);                                        \
    CP16(d_ + ((1u ^ fx) << 4), s_ + 8);                                        \
    CP16(d_ + ((2u ^ fx) << 4), s_ + 16);                                       \
    CP16(d_ + ((3u ^ fx) << 4), s_ + 24);                                       \
} while (0)

    float acc[4][4][4];
#pragma unroll
    for (int mt = 0; mt < 4; mt++)
#pragma unroll
        for (int nt = 0; nt < 4; nt++)
#pragma unroll
            for (int j = 0; j < 4; j++) acc[mt][nt][j] = 0.f;

    FETCH(0, 0); CP_COMMIT();
    FETCH(1, 1); CP_COMMIT();

    int stage = 0;
    for (int c = 0; c < nch; c++) {
        int fs = c + 2;
        if (fs < nch) { int st = fs - (fs / 3) * 3; FETCH(st, fs); }
        CP_COMMIT();
        CP_WAIT2();
        __syncthreads();

        uint32_t sa = sbase + stage * STG;
#pragma unroll
        for (int h = 0; h < 2; h++) {
            uint32_t ah[4][4];
            uint32_t cA = (uint32_t)(((h * 2 + kbA) ^ selA) << 4);
#pragma unroll
            for (int mt = 0; mt < 4; mt++)
                LDM4(ah[mt], sa + (uint32_t)((wm + mt * 16 + rlA) * 64) + cA);
            uint32_t cB = (uint32_t)(((h * 2 + kbB) ^ selB) << 4);
#pragma unroll
            for (int np = 0; np < 2; np++) {
                uint32_t bh[4];
                LDM4(bh, sa + 8192u + (uint32_t)((wn + np * 16 + rlB) * 64) + cB);
#pragma unroll
                for (int q = 0; q < 2; q++) {
                    int nt = np * 2 + q;
#pragma unroll
                    for (int mt = 0; mt < 4; mt++)
                        mma16816(acc[mt][nt], ah[mt][0], ah[mt][1], ah[mt][2], ah[mt][3],
                                 bh[q * 2], bh[q * 2 + 1]);
                }
            }
        }
        __syncthreads();
        stage++; if (stage == 3) stage = 0;
    }

#pragma unroll
    for (int mt = 0; mt < 4; mt++) {
#pragma unroll
        for (int half = 0; half < 2; half++) {
            int r = brow + wm + mt * 16 + g + half * 8;
#pragma unroll
            for (int nt = 0; nt < 4; nt++) {
                int col = bcol + wn + nt * 8 + tg * 2;
                float v0 = acc[mt][nt][half * 2 + 0] + __ldg(&bias[col + 0]);
                float v1 = acc[mt][nt][half * 2 + 1] + __ldg(&bias[col + 1]);
                if (relu) { v0 = fmaxf(v0, 0.f); v1 = fmaxf(v1, 0.f); }
                size_t off = (size_t)r * N + col;
                if (resid) {
                    float2 rv = *(const float2*)(resid + off);
                    v0 += rv.x; v1 += rv.y;
                }
                if (Cp) {
                    __half2 hv;
                    hv.x = __float2half(v0);
                    hv.y = __float2half(v1);
                    *(__half2*)(Cp + off) = hv;
                } else {
                    float2 fv; fv.x = v0; fv.y = v1;
                    *(float2*)(C + off) = fv;
                }
            }
        }
    }
}

// ---------------- weight transpose: out[n][k] = fp16(in[k][n]) ----------------
__global__ void __launch_bounds__(256) transpose_pack_kernel(const float* __restrict__ in,
                                                             __half* __restrict__ out,
                                                             int R, int Ccols) {
    __shared__ float t[32][33];
    int bx = blockIdx.x * 32, by = blockIdx.y * 32;
    int x = threadIdx.x & 31, y = threadIdx.x >> 5;
#pragma unroll
    for (int j = 0; j < 32; j += 8)
        t[y + j][x] = in[(size_t)(by + y + j) * Ccols + bx + x];
    __syncthreads();
#pragma unroll
    for (int j = 0; j < 32; j += 8)
        out[(size_t)(bx + y + j) * R + by + x] = __float2half(t[x][y + j]);
}

__global__ void __launch_bounds__(256) transpose_qkv_kernel(const float* __restrict__ Wq,
                                                            const float* __restrict__ Wk,
                                                            const float* __restrict__ Wv,
                                                            __half* __restrict__ out) {
    const float* in = (blockIdx.z == 0) ? Wq : (blockIdx.z == 1) ? Wk : Wv;
    __half* dst = out + (size_t)blockIdx.z * DMODEL * DMODEL;
    __shared__ float t[32][33];
    int bx = blockIdx.x * 32, by = blockIdx.y * 32;
    int x = threadIdx.x & 31, y = threadIdx.x >> 5;
#pragma unroll
    for (int j = 0; j < 32; j += 8)
        t[y + j][x] = in[(size_t)(by + y + j) * DMODEL + bx + x];
    __syncthreads();
#pragma unroll
    for (int j = 0; j < 32; j += 8)
        dst[(size_t)(bx + y + j) * DMODEL + by + x] = __float2half(t[x][y + j]);
}

__global__ void bias_concat_kernel(const float* __restrict__ bq,
                                   const float* __restrict__ bk,
                                   const float* __restrict__ bv,
                                   float* __restrict__ bqkv) {
    int t = blockIdx.x * 256 + threadIdx.x;
    if (t < DMODEL)            bqkv[t] = bq[t];
    else if (t < 2 * DMODEL)   bqkv[t] = bk[t - DMODEL];
    else if (t < 3 * DMODEL)   bqkv[t] = bv[t - 2 * DMODEL];
}

// ---------------- LayerNorm -> fp16 ----------------
__global__ void __launch_bounds__(256) ln_pack_kernel(const float* __restrict__ x,
                                                      const float* __restrict__ gam,
                                                      const float* __restrict__ bet,
                                                      __half* __restrict__ out) {
    int row = blockIdx.x;
    const float* xr = x + (size_t)row * DMODEL;
    int t = threadIdx.x;
    float v0 = xr[t], v1 = xr[t + 256], v2 = xr[t + 512];
    float s  = v0 + v1 + v2;
    float sq = v0 * v0 + v1 * v1 + v2 * v2;
#pragma unroll
    for (int o = 16; o; o >>= 1) {
        s  += __shfl_xor_sync(0xffffffffu, s, o);
        sq += __shfl_xor_sync(0xffffffffu, sq, o);
    }
    __shared__ float rs_[8], rq_[8];
    if ((t & 31) == 0) { rs_[t >> 5] = s; rq_[t >> 5] = sq; }
    __syncthreads();
    s = 0.f; sq = 0.f;
#pragma unroll
    for (int ww = 0; ww < 8; ww++) { s += rs_[ww]; sq += rq_[ww]; }
    float m   = s * (1.f / DMODEL);
    float var = sq * (1.f / DMODEL) - m * m;
    float inv = rsqrtf(var + 1e-5f);
    __half* orow = out + (size_t)row * DMODEL;
    orow[t]       = __float2half((v0 - m) * inv * gam[t]       + bet[t]);
    orow[t + 256] = __float2half((v1 - m) * inv * gam[t + 256] + bet[t + 256]);
    orow[t + 512] = __float2half((v2 - m) * inv * gam[t + 512] + bet[t + 512]);
}

// ---------------- tensor-core BigBird attention ----------------
// per CTA (block i, head hh, batch b), 256 thr = 8 warps.
// smem: Q[64][104h] K[320][104h] V[320][104h] P[64][328h] + stats
#define ARS 208            // 104 halfs row stride (bytes)
#define PRS 656            // 328 halfs row stride (bytes)
#define AOFF_Q 0
#define AOFF_K 13312
#define AOFF_V 79872
#define AOFF_P 146432
#define AOFF_MX 188416
#define AOFF_SM (188416 + 512)
#define ATTN_SMEM (188416 + 1024)

__global__ void __launch_bounds__(256) attn_tc_kernel(const __half* __restrict__ QKV,
                                                      const int* __restrict__ kb_idx,
                                                      __half* __restrict__ ctxP) {
    extern __shared__ char sm[];
    uint32_t sb = smem_u32(sm);
    float* smax = (float*)(sm + AOFF_MX);
    float* ssum = (float*)(sm + AOFF_SM);

    int i  = blockIdx.x;
    int hh = blockIdx.y;
    int b  = blockIdx.z;
    int tid = threadIdx.x;
    int w = tid >> 5, lane = tid & 31;
    int g = lane >> 2, tg = lane & 3;
    int wm = (w >> 1) * 16;
    int half_ = w & 1;
    int base = b * SEQ + i * BLKS;

    int rlA = (lane & 7) + ((lane >> 3) & 1) * 8;
    int kbA = (lane >> 4) & 1;
    int rlB = (lane & 7) + ((lane >> 4) & 1) * 8;
    int kbB = (lane >> 3) & 1;

    int  kbv[NKBS];
    bool val[NKBS], dia[NKBS];
#pragma unroll
    for (int s = 0; s < NKBS; s++) {
        kbv[s] = kb_idx[i * NKBS + s];
        val[s] = (s == 0) || (kbv[s] != 0);
        dia[s] = (kbv[s] == i);
    }

    const __half* Qg = QKV + hh * HDIM;
    const __half* Kg = QKV + DMODEL + hh * HDIM;
    const __half* Vg = QKV + 2 * DMODEL + hh * HDIM;

    // gather Q (64 x 96 = 768 uint4)
    for (int idx = tid; idx < 768; idx += 256) {
        int r = idx / 12, c = idx % 12;
        uint4 v = *(const uint4*)(Qg + (size_t)(base + r) * NQKV + c * 8);
        *(uint4*)(sm + AOFF_Q + r * ARS + c * 16) = v;
    }
    // gather K,V (5 slots x 64 x 96)
    for (int idx = tid; idx < 3840; idx += 256) {
        int s = idx / 768, rr = (idx % 768) / 12, c = idx % 12;
        int krow = s * 64 + rr;
        if (val[s]) {
            size_t gr = (size_t)(b * SEQ + kbv[s] * 64 + rr) * NQKV;
            *(uint4*)(sm + AOFF_K + krow * ARS + c * 16) = *(const uint4*)(Kg + gr + c * 8);
            *(uint4*)(sm + AOFF_V + krow * ARS + c * 16) = *(const uint4*)(Vg + gr + c * 8);
        } else {
            uint4 z; z.x = 0; z.y = 0; z.z = 0; z.w = 0;
            *(uint4*)(sm + AOFF_V + krow * ARS + c * 16) = z;
        }
    }
    __syncthreads();

    // ---- scores: [wm..wm+16) x [wn..wn+160), K = 96 ----
    int wn = half_ * 160;
    float acc[10][2][4];
#pragma unroll
    for (int np = 0; np < 10; np++)
#pragma unroll
        for (int q = 0; q < 2; q++)
#pragma unroll
            for (int j = 0; j < 4; j++) acc[np][q][j] = 0.f;

#pragma unroll
    for (int t = 0; t < 6; t++) {
        uint32_t ah[4];
        LDM4(ah, sb + AOFF_Q + (uint32_t)((wm + rlA) * ARS) + t * 32 + kbA * 16);
#pragma unroll
        for (int np = 0; np < 10; np++) {
            uint32_t bh[4];
            LDM4(bh, sb + AOFF_K + (uint32_t)((wn + np * 16 + rlB) * ARS) + t * 32 + kbB * 16);
            mma16816(acc[np][0], ah[0], ah[1], ah[2], ah[3], bh[0], bh[1]);
            mma16816(acc[np][1], ah[0], ah[1], ah[2], ah[3], bh[2], bh[3]);
        }
    }

    const float scale = rsqrtf((float)HDIM);
#pragma unroll
    for (int np = 0; np < 10; np++)
#pragma unroll
        for (int q = 0; q < 2; q++)
#pragma unroll
            for (int j = 0; j < 4; j++) {
                int col = wn + np * 16 + q * 8 + tg * 2 + (j & 1);
                int row = wm + g + 8 * (j >> 1);
                int s = col >> 6, p = col & 63;
                float v = acc[np][q][j] * scale;
                if (!val[s] || (dia[s] && p > row)) v = -1e9f;
                acc[np][q][j] = v;
            }

    // row max (quad shuffle + cross-warp)
    float m0 = -1e30f, m1 = -1e30f;
#pragma unroll
    for (int np = 0; np < 10; np++)
#pragma unroll
        for (int q = 0; q < 2; q++) {
            m0 = fmaxf(m0, fmaxf(acc[np][q][0], acc[np][q][1]));
            m1 = fmaxf(m1, fmaxf(acc[np][q][2], acc[np][q][3]));
        }
    m0 = fmaxf(m0, __shfl_xor_sync(0xffffffffu, m0, 1));
    m0 = fmaxf(m0, __shfl_xor_sync(0xffffffffu, m0, 2));
    m1 = fmaxf(m1, __shfl_xor_sync(0xffffffffu, m1, 1));
    m1 = fmaxf(m1, __shfl_xor_sync(0xffffffffu, m1, 2));
    if (tg == 0) {
        smax[(wm + g) * 2 + half_]     = m0;
        smax[(wm + g + 8) * 2 + half_] = m1;
    }
    __syncthreads();
    float M0 = fmaxf(smax[(wm + g) * 2],     smax[(wm + g) * 2 + 1]);
    float M1 = fmaxf(smax[(wm + g + 8) * 2], smax[(wm + g + 8) * 2 + 1]);

    // exp, sums, store P (fp16)
    float s0 = 0.f, s1 = 0.f;
#pragma unroll
    for (int np = 0; np < 10; np++)
#pragma unroll
        for (int q = 0; q < 2; q++) {
            float e0 = __expf(acc[np][q][0] - M0);
            float e1 = __expf(acc[np][q][1] - M0);
            float e2 = __expf(acc[np][q][2] - M1);
            float e3 = __expf(acc[np][q][3] - M1);
            s0 += e0 + e1; s1 += e2 + e3;
            int colb = (wn + np * 16 + q * 8 + tg * 2) * 2;
            __half2 h01; h01.x = __float2half(e0); h01.y = __float2half(e1);
            __half2 h23; h23.x = __float2half(e2); h23.y = __float2half(e3);
            *(__half2*)(sm + AOFF_P + (wm + g) * PRS + colb)     = h01;
            *(__half2*)(sm + AOFF_P + (wm + g + 8) * PRS + colb) = h23;
        }
    s0 += __shfl_xor_sync(0xffffffffu, s0, 1);
    s0 += __shfl_xor_sync(0xffffffffu, s0, 2);
    s1 += __shfl_xor_sync(0xffffffffu, s1, 1);
    s1 += __shfl_xor_sync(0xffffffffu, s1, 2);
    if (tg == 0) {
        ssum[(wm + g) * 2 + half_]     = s0;
        ssum[(wm + g + 8) * 2 + half_] = s1;
    }
    __syncthreads();
    float r0 = 1.f / (ssum[(wm + g) * 2]     + ssum[(wm + g) * 2 + 1]);
    float r1 = 1.f / (ssum[(wm + g + 8) * 2] + ssum[(wm + g + 8) * 2 + 1]);

    // ---- PV: ctx[wm..16) x [vn..vn+48), K = 320 ----
    int vn = half_ * 48;
    float cacc[3][2][4];
#pragma unroll
    for (int np = 0; np < 3; np++)
#pragma unroll
        for (int q = 0; q < 2; q++)
#pragma unroll
            for (int j = 0; j < 4; j++) cacc[np][q][j] = 0.f;

#pragma unroll 4
    for (int t = 0; t < 20; t++) {
        uint32_t ph[4];
        LDM4(ph, sb + AOFF_P + (uint32_t)((wm + rlA) * PRS) + t * 32 + kbA * 16);
#pragma unroll
        for (int np = 0; np < 3; np++) {
            uint32_t bh[4];
            LDM4T(bh, sb + AOFF_V + (uint32_t)((t * 16 + (lane & 15)) * ARS)
                      + (vn + np * 16 + ((lane >> 4) & 1) * 8) * 2);
            mma16816(cacc[np][0], ph[0], ph[1], ph[2], ph[3], bh[0], bh[1]);
            mma16816(cacc[np][1], ph[0], ph[1], ph[2], ph[3], bh[2], bh[3]);
        }
    }

    // write ctx fp16
#pragma unroll
    for (int np = 0; np < 3; np++)
#pragma unroll
        for (int q = 0; q < 2; q++) {
            int d0 = vn + np * 16 + q * 8 + tg * 2;
            size_t o0 = (size_t)(base + wm + g) * DMODEL + hh * HDIM + d0;
            size_t o1 = (size_t)(base + wm + g + 8) * DMODEL + hh * HDIM + d0;
            __half2 h01; h01.x = __float2half(cacc[np][q][0] * r0);
            h01.y = __float2half(cacc[np][q][1] * r0);
            __half2 h23; h23.x = __float2half(cacc[np][q][2] * r1);
            h23.y = __float2half(cacc[np][q][3] * r1);
            *(__half2*)(ctxP + o0) = h01;
            *(__half2*)(ctxP + o1) = h23;
        }
}

// ---------------- host launcher ----------------
extern "C" void kernel_launch(void* const* d_in, const int* in_sizes, int n_in,
                              void* d_out, int out_size) {
    const float* x    = (const float*)d_in[0];
    const float* Wq   = (const float*)d_in[1];
    const float* bq   = (const float*)d_in[2];
    const float* Wk   = (const float*)d_in[3];
    const float* bk   = (const float*)d_in[4];
    const float* Wv   = (const float*)d_in[5];
    const float* bv   = (const float*)d_in[6];
    const float* Wo   = (const float*)d_in[7];
    const float* bo   = (const float*)d_in[8];
    const float* ln_g = (const float*)d_in[9];
    const float* ln_b = (const float*)d_in[10];
    const float* W1   = (const float*)d_in[11];
    const float* b1   = (const float*)d_in[12];
    const float* W2   = (const float*)d_in[13];
    const float* b2   = (const float*)d_in[14];
    const int*   kb   = (const int*)d_in[15];
    float* out = (float*)d_out;

    __half *phP, *pctxP, *pffnP, *pqkvh, *wqkvT, *woT, *w1T, *w2T;
    float *px, *pbqkv;
    cudaGetSymbolAddress((void**)&phP,   g_hP);
    cudaGetSymbolAddress((void**)&pctxP, g_ctxP);
    cudaGetSymbolAddress((void**)&pffnP, g_ffnP);
    cudaGetSymbolAddress((void**)&pqkvh, g_qkvh);
    cudaGetSymbolAddress((void**)&px,    g_x);
    cudaGetSymbolAddress((void**)&wqkvT, g_wqkvT);
    cudaGetSymbolAddress((void**)&woT,   g_woT);
    cudaGetSymbolAddress((void**)&w1T,   g_w1T);
    cudaGetSymbolAddress((void**)&w2T,   g_w2T);
    cudaGetSymbolAddress((void**)&pbqkv, g_bqkv);

    cudaFuncSetAttribute(attn_tc_kernel, cudaFuncAttributeMaxDynamicSharedMemorySize,
                         ATTN_SMEM);
    cudaFuncSetAttribute(gemm_h1_kernel, cudaFuncAttributeMaxDynamicSharedMemorySize,
                         GSMEM);

    dim3 tDD(DMODEL / 32, DMODEL / 32);
    dim3 gQKV(NQKV / 128, TOKENS / 128);
    dim3 gWo (DMODEL / 128, TOKENS / 128);
    dim3 gF1 (DFFN / 128, TOKENS / 128);

    // ncu -s 5 with 2 harness-injected launches samples OUR kernel index 3 = QKV GEMM
    ln_pack_kernel<<<TOKENS, 256>>>(x, ln_g, ln_b, phP);                           // 0
    transpose_qkv_kernel<<<dim3(DMODEL / 32, DMODEL / 32, 3), 256>>>(Wq, Wk, Wv,   // 1
                                                                     wqkvT);
    bias_concat_kernel<<<(NQKV + 255) / 256, 256>>>(bq, bk, bv, pbqkv);            // 2
    gemm_h1_kernel<<<gQKV, 256, GSMEM>>>(phP, wqkvT, pbqkv, nullptr, nullptr,      // 3 <- ncu
                                         pqkvh, DMODEL, NQKV, 0);
    transpose_pack_kernel<<<tDD, 256>>>(Wo, woT, DMODEL, DMODEL);                  // 4
    attn_tc_kernel<<<dim3(NBLK, NHEAD, BATCH), 256, ATTN_SMEM>>>(pqkvh, kb,        // 5
                                                                 pctxP);
    gemm_h1_kernel<<<gWo, 256, GSMEM>>>(pctxP, woT, bo, x, px, nullptr,            // 6
                                        DMODEL, DMODEL, 0);
    ln_pack_kernel<<<TOKENS, 256>>>(px, ln_g, ln_b, phP);                          // 7
    transpose_pack_kernel<<<dim3(DFFN / 32, DMODEL / 32), 256>>>(W1, w1T,          // 8
                                                                 DMODEL, DFFN);
    transpose_pack_kernel<<<dim3(DMODEL / 32, DFFN / 32), 256>>>(W2, w2T,          // 9
                                                                 DFFN, DMODEL);
    gemm_h1_kernel<<<gF1, 256, GSMEM>>>(phP, w1T, b1, nullptr, nullptr, pffnP,     // 10
                                        DMODEL, DFFN, 1);
    gemm_h1_kernel<<<gWo, 256, GSMEM>>>(pffnP, w2T, b2, px, out, nullptr,          // 11
                                        DFFN, DMODEL, 0);
}